// round 5
// baseline (speedup 1.0000x reference)
#include <cuda_runtime.h>

#define EMBD   384
#define FFN_D  1536
#define T_SEQ  200
#define NH     6
#define HS     64
#define BATCH  256
#define M_ROWS (BATCH * T_SEQ)   // 51200

// ---------------- scratch (no allocations allowed) ----------------
__device__ float g_H [M_ROWS * EMBD];
__device__ float g_Q [M_ROWS * EMBD];
__device__ float g_K [M_ROWS * EMBD];
__device__ float g_V [M_ROWS * EMBD];
__device__ float g_A [M_ROWS * EMBD];
__device__ float g_X1[M_ROWS * EMBD];
__device__ float g_F [M_ROWS * FFN_D];

// ---------------- LayerNorm (one block per row of 384) ----------------
__global__ void ln_kernel(const float* __restrict__ x,
                          const float* __restrict__ g,
                          const float* __restrict__ be,
                          float* __restrict__ out)
{
    __shared__ float red[4];
    int row = blockIdx.x;
    int t = threadIdx.x;               // 128 threads, 3 elems each
    const float* xr = x + (size_t)row * EMBD;

    float v0 = xr[t], v1 = xr[t + 128], v2 = xr[t + 256];
    float s = v0 + v1 + v2;
    #pragma unroll
    for (int o = 16; o; o >>= 1) s += __shfl_xor_sync(0xffffffffu, s, o);
    if ((t & 31) == 0) red[t >> 5] = s;
    __syncthreads();
    float mean = (red[0] + red[1] + red[2] + red[3]) * (1.0f / EMBD);
    __syncthreads();

    float d0 = v0 - mean, d1 = v1 - mean, d2 = v2 - mean;
    float sq = d0 * d0 + d1 * d1 + d2 * d2;
    #pragma unroll
    for (int o = 16; o; o >>= 1) sq += __shfl_xor_sync(0xffffffffu, sq, o);
    if ((t & 31) == 0) red[t >> 5] = sq;
    __syncthreads();
    float var = (red[0] + red[1] + red[2] + red[3]) * (1.0f / EMBD);
    float inv = rsqrtf(var + 1e-5f);

    float* orow = out + (size_t)row * EMBD;
    orow[t]       = d0 * inv * g[t]       + be[t];
    orow[t + 128] = d1 * inv * g[t + 128] + be[t + 128];
    orow[t + 256] = d2 * inv * g[t + 256] + be[t + 256];
}

// ---------------- Tiled SGEMM: C(M,N) = A(M,K) @ B(K,N) [+epilogue] ----------------
// EPI: 0 = none, 1 = bias + relu, 2 = bias + residual add
// 256 threads, 64x64 tile, BK=16, 4x4 per-thread microtile.
template <int EPI>
__global__ void gemm_kernel(const float* __restrict__ A,
                            const float* __restrict__ Bw,
                            const float* __restrict__ bias,
                            const float* __restrict__ add,
                            float* __restrict__ C,
                            int M, int N, int K)
{
    __shared__ float As[16 * 68];   // transposed A tile, stride 68 (pad: conflicts + 16B align)
    __shared__ float Bs[16 * 64];

    int tid = threadIdx.x;
    int tx = tid & 15, ty = tid >> 4;
    int m0 = blockIdx.y * 64, n0 = blockIdx.x * 64;

    float acc[4][4] = {};

    // A tile load: thread -> (row am, 4 consecutive k at ak)
    int am = tid >> 2, ak = (tid & 3) * 4;
    // B tile load: thread -> (k-row bk, 4 consecutive n at bn)
    int bk = tid >> 4, bn = (tid & 15) * 4;

    const float* Ag = A + (size_t)(m0 + am) * K + ak;
    const float* Bg = Bw + (size_t)bk * N + n0 + bn;

    for (int k0 = 0; k0 < K; k0 += 16) {
        float4 a4 = *(const float4*)(Ag + k0);
        float4 b4 = *(const float4*)(Bg + (size_t)k0 * N);
        *(float4*)&Bs[bk * 64 + bn] = b4;
        As[(ak + 0) * 68 + am] = a4.x;
        As[(ak + 1) * 68 + am] = a4.y;
        As[(ak + 2) * 68 + am] = a4.z;
        As[(ak + 3) * 68 + am] = a4.w;
        __syncthreads();

        #pragma unroll
        for (int k = 0; k < 16; k++) {
            float4 av = *(const float4*)&As[k * 68 + ty * 4];
            float4 bv = *(const float4*)&Bs[k * 64 + tx * 4];
            float a[4] = {av.x, av.y, av.z, av.w};
            float b[4] = {bv.x, bv.y, bv.z, bv.w};
            #pragma unroll
            for (int i = 0; i < 4; i++)
                #pragma unroll
                for (int j = 0; j < 4; j++)
                    acc[i][j] += a[i] * b[j];
        }
        __syncthreads();
    }

    float bx[4];
    if (EPI != 0) {
        #pragma unroll
        for (int j = 0; j < 4; j++) bx[j] = bias[n0 + tx * 4 + j];
    }
    #pragma unroll
    for (int i = 0; i < 4; i++) {
        int r = m0 + ty * 4 + i;
        size_t off = (size_t)r * N + n0 + tx * 4;
        float v[4];
        #pragma unroll
        for (int j = 0; j < 4; j++) v[j] = acc[i][j];
        if (EPI == 1) {
            #pragma unroll
            for (int j = 0; j < 4; j++) v[j] = fmaxf(v[j] + bx[j], 0.0f);
        } else if (EPI == 2) {
            float4 r4 = *(const float4*)(add + off);
            v[0] += bx[0] + r4.x; v[1] += bx[1] + r4.y;
            v[2] += bx[2] + r4.z; v[3] += bx[3] + r4.w;
        }
        float4 o4 = {v[0], v[1], v[2], v[3]};
        *(float4*)(C + off) = o4;
    }
}

// ---------------- Attention: one block per (batch, head) ----------------
// SMEM: K (pad 65), V (stride 64), per-warp scores + q row.
#define ATTN_SMEM ((T_SEQ * 65 + T_SEQ * 64 + 8 * T_SEQ + 8 * HS) * 4)

__global__ void attn_kernel(const float* __restrict__ Q,
                            const float* __restrict__ K,
                            const float* __restrict__ V,
                            float* __restrict__ O)
{
    extern __shared__ float sm[];
    float* Ks  = sm;                       // T_SEQ * 65
    float* Vs  = Ks + T_SEQ * 65;          // T_SEQ * 64
    float* Ssc = Vs + T_SEQ * 64;          // 8 * T_SEQ
    float* Qs  = Ssc + 8 * T_SEQ;          // 8 * HS

    int bh = blockIdx.x;
    int b = bh / NH, h = bh % NH;
    int tid = threadIdx.x;

    const float* Kg = K + (size_t)(b * T_SEQ) * EMBD + h * HS;
    const float* Vg = V + (size_t)(b * T_SEQ) * EMBD + h * HS;
    for (int i = tid; i < T_SEQ * HS; i += blockDim.x) {
        int j = i >> 6, d = i & 63;
        Ks[j * 65 + d] = Kg[(size_t)j * EMBD + d];
        Vs[j * 64 + d] = Vg[(size_t)j * EMBD + d];
    }
    __syncthreads();

    int warp = tid >> 5, lane = tid & 31;
    float* myS = Ssc + warp * T_SEQ;
    float* myQ = Qs + warp * HS;
    const float scale = 0.05103103630798288f;   // 384^-0.5

    for (int t = warp; t < T_SEQ; t += 8) {
        const float* qrow = Q + (size_t)(b * T_SEQ + t) * EMBD + h * HS;
        myQ[lane]      = qrow[lane];
        myQ[lane + 32] = qrow[lane + 32];
        __syncwarp();

        for (int j = lane; j <= t; j += 32) {
            float s = 0.f;
            #pragma unroll
            for (int d = 0; d < HS; d++) s += myQ[d] * Ks[j * 65 + d];
            myS[j] = s * scale;
        }
        __syncwarp();

        float m = -1e30f;
        for (int j = lane; j <= t; j += 32) m = fmaxf(m, myS[j]);
        #pragma unroll
        for (int o = 16; o; o >>= 1) m = fmaxf(m, __shfl_xor_sync(0xffffffffu, m, o));

        float sum = 0.f;
        for (int j = lane; j <= t; j += 32) {
            float p = __expf(myS[j] - m);
            myS[j] = p;
            sum += p;
        }
        #pragma unroll
        for (int o = 16; o; o >>= 1) sum += __shfl_xor_sync(0xffffffffu, sum, o);
        __syncwarp();
        float inv = 1.f / sum;

        float a0 = 0.f, a1 = 0.f;
        for (int j = 0; j <= t; j++) {
            float p = myS[j];
            a0 += p * Vs[j * 64 + lane];
            a1 += p * Vs[j * 64 + lane + 32];
        }
        float* orow = O + (size_t)(b * T_SEQ + t) * EMBD + h * HS;
        orow[lane]      = a0 * inv;
        orow[lane + 32] = a1 * inv;
        __syncwarp();
    }
}

// ---------------- launch ----------------
extern "C" void kernel_launch(void* const* d_in, const int* in_sizes, int n_in,
                              void* d_out, int out_size)
{
    const float* x     = (const float*)d_in[0];
    const float* Wq    = (const float*)d_in[1];
    const float* Wk    = (const float*)d_in[2];
    const float* Wv    = (const float*)d_in[3];
    const float* Wproj = (const float*)d_in[4];
    const float* bproj = (const float*)d_in[5];
    const float* W1    = (const float*)d_in[6];
    const float* b1    = (const float*)d_in[7];
    const float* W2    = (const float*)d_in[8];
    const float* b2    = (const float*)d_in[9];
    const float* g1    = (const float*)d_in[10];
    const float* be1   = (const float*)d_in[11];
    const float* g2    = (const float*)d_in[12];
    const float* be2   = (const float*)d_in[13];

    float *H, *Q, *K, *V, *A, *X1, *F;
    cudaGetSymbolAddress((void**)&H,  g_H);
    cudaGetSymbolAddress((void**)&Q,  g_Q);
    cudaGetSymbolAddress((void**)&K,  g_K);
    cudaGetSymbolAddress((void**)&V,  g_V);
    cudaGetSymbolAddress((void**)&A,  g_A);
    cudaGetSymbolAddress((void**)&X1, g_X1);
    cudaGetSymbolAddress((void**)&F,  g_F);

    cudaFuncSetAttribute(attn_kernel,
                         cudaFuncAttributeMaxDynamicSharedMemorySize, ATTN_SMEM);

    dim3 blk(256);
    dim3 g384(EMBD / 64, M_ROWS / 64);
    dim3 gffn(FFN_D / 64, M_ROWS / 64);

    // 1) h = LN(x)
    ln_kernel<<<M_ROWS, 128>>>(x, g1, be1, H);
    // 2) q,k,v = h @ W{q,k,v}
    gemm_kernel<0><<<g384, blk>>>(H, Wq, nullptr, nullptr, Q, M_ROWS, EMBD, EMBD);
    gemm_kernel<0><<<g384, blk>>>(H, Wk, nullptr, nullptr, K, M_ROWS, EMBD, EMBD);
    gemm_kernel<0><<<g384, blk>>>(H, Wv, nullptr, nullptr, V, M_ROWS, EMBD, EMBD);
    // 3) att = softmax(causal(q k^T * scale)) v
    attn_kernel<<<BATCH * NH, blk, ATTN_SMEM>>>(Q, K, V, A);
    // 4) x1 = x + att @ Wproj + bproj
    gemm_kernel<2><<<g384, blk>>>(A, Wproj, bproj, x, X1, M_ROWS, EMBD, EMBD);
    // 5) h2 = LN(x1)
    ln_kernel<<<M_ROWS, 128>>>(X1, g2, be2, H);
    // 6) f = relu(h2 @ W1 + b1)
    gemm_kernel<1><<<gffn, blk>>>(H, W1, b1, nullptr, F, M_ROWS, FFN_D, EMBD);
    // 7) out = x1 + f @ W2 + b2
    gemm_kernel<2><<<g384, blk>>>(F, W2, b2, X1, (float*)d_out, M_ROWS, EMBD, FFN_D);
}

// round 6
// speedup vs baseline: 2.5510x; 2.5510x over previous
#include <cuda_runtime.h>
#include <cstdint>

#define EMBD   384
#define FFN_D  1536
#define T_SEQ  200
#define NH     6
#define HS     64
#define BATCH  256
#define M_ROWS (BATCH * T_SEQ)   // 51200

// ---------------- scratch (no allocations allowed) ----------------
__device__ float g_H [M_ROWS * EMBD];
__device__ float g_Q [M_ROWS * EMBD];
__device__ float g_K [M_ROWS * EMBD];
__device__ float g_V [M_ROWS * EMBD];
__device__ float g_A [M_ROWS * EMBD];
__device__ float g_X1[M_ROWS * EMBD];
__device__ float g_F [M_ROWS * FFN_D];

// ---------------- helpers ----------------
__device__ __forceinline__ uint32_t f2tf32(float f) {
    uint32_t r;
    asm("cvt.rna.tf32.f32 %0, %1;" : "=r"(r) : "f"(f));
    return r;
}

__device__ __forceinline__ void cp16(void* dst_smem, const void* src) {
    uint32_t d = (uint32_t)__cvta_generic_to_shared(dst_smem);
    asm volatile("cp.async.cg.shared.global [%0], [%1], 16;" :: "r"(d), "l"(src));
}
#define CP_COMMIT()  asm volatile("cp.async.commit_group;")
#define CP_WAIT(n)   asm volatile("cp.async.wait_group %0;" :: "n"(n))

// ---------------- LayerNorm (one block per row of 384) ----------------
__global__ void ln_kernel(const float* __restrict__ x,
                          const float* __restrict__ g,
                          const float* __restrict__ be,
                          float* __restrict__ out)
{
    __shared__ float red[4];
    int row = blockIdx.x;
    int t = threadIdx.x;               // 128 threads, 3 elems each
    const float* xr = x + (size_t)row * EMBD;

    float v0 = xr[t], v1 = xr[t + 128], v2 = xr[t + 256];
    float s = v0 + v1 + v2;
    #pragma unroll
    for (int o = 16; o; o >>= 1) s += __shfl_xor_sync(0xffffffffu, s, o);
    if ((t & 31) == 0) red[t >> 5] = s;
    __syncthreads();
    float mean = (red[0] + red[1] + red[2] + red[3]) * (1.0f / EMBD);
    __syncthreads();

    float d0 = v0 - mean, d1 = v1 - mean, d2 = v2 - mean;
    float sq = d0 * d0 + d1 * d1 + d2 * d2;
    #pragma unroll
    for (int o = 16; o; o >>= 1) sq += __shfl_xor_sync(0xffffffffu, sq, o);
    if ((t & 31) == 0) red[t >> 5] = sq;
    __syncthreads();
    float var = (red[0] + red[1] + red[2] + red[3]) * (1.0f / EMBD);
    float inv = rsqrtf(var + 1e-5f);

    float* orow = out + (size_t)row * EMBD;
    orow[t]       = d0 * inv * g[t]       + be[t];
    orow[t + 128] = d1 * inv * g[t + 128] + be[t + 128];
    orow[t + 256] = d2 * inv * g[t + 256] + be[t + 256];
}

// ---------------- TF32 tensor-core GEMM ----------------
// C(M,N) = A(M,K) @ B(K,N)  [+ epilogue]
// EPI: 0 = none, 1 = bias + relu, 2 = bias + residual add
// CTA tile 128x128, BK=16, 256 threads = 8 warps (4 M x 2 N),
// warp tile 32x64 = 2x8 mma.m16n8k8 tiles. 2-stage cp.async pipeline.
// Requires: M%128==0, N%128==0, K%16==0 (true for all 6 calls).
#define A_STRIDE 20    // 16 + 4 pad: (gid*20+tig)%32 hits 8 distinct bank groups
#define B_STRIDE 136   // 128 + 8 pad: (tig*136+gid)%32 = 8*tig+gid, conflict-free

template <int EPI>
__global__ void __launch_bounds__(256)
gemm_tc(const float* __restrict__ A,
        const float* __restrict__ Bw,
        const float* __restrict__ bias,
        const float* __restrict__ add,
        float* __restrict__ C,
        int M, int N, int K)
{
    __shared__ float As[2][128 * A_STRIDE];
    __shared__ float Bs[2][16 * B_STRIDE];

    const int tid  = threadIdx.x;
    const int warp = tid >> 5, lane = tid & 31;
    const int wm   = warp >> 1, wn = warp & 1;       // 4 x 2 warp grid
    const int gid  = lane >> 2, tig = lane & 3;      // mma fragment coords
    const int m0   = blockIdx.y * 128, n0 = blockIdx.x * 128;

    // A stage-load mapping: 128 rows x 16 k = 512 float4 chunks, 2 per thread
    const int am  = tid >> 2;            // rows am and am+64
    const int ak  = (tid & 3) * 4;       // k offset (float4)
    // B stage-load mapping: 16 k-rows x 128 n = 512 float4 chunks, 2 per thread
    const int bk  = tid >> 5;            // k rows bk and bk+8
    const int bn  = (tid & 31) * 4;      // n offset (float4)

    float acc[2][8][4];
    #pragma unroll
    for (int i = 0; i < 2; i++)
        #pragma unroll
        for (int j = 0; j < 8; j++)
            #pragma unroll
            for (int l = 0; l < 4; l++) acc[i][j][l] = 0.f;

    const int nstages = K / 16;

    auto load_stage = [&](int buf, int k0) {
        #pragma unroll
        for (int s = 0; s < 2; s++) {
            const float* src = A + (size_t)(m0 + am + s * 64) * K + k0 + ak;
            cp16(&As[buf][(am + s * 64) * A_STRIDE + ak], src);
        }
        #pragma unroll
        for (int s = 0; s < 2; s++) {
            const float* src = Bw + (size_t)(k0 + bk + s * 8) * N + n0 + bn;
            cp16(&Bs[buf][(bk + s * 8) * B_STRIDE + bn], src);
        }
        CP_COMMIT();
    };

    load_stage(0, 0);
    int buf = 0;

    for (int s = 0; s < nstages; s++) {
        if (s + 1 < nstages) {
            load_stage(buf ^ 1, (s + 1) * 16);
            CP_WAIT(1);
        } else {
            CP_WAIT(0);
        }
        __syncthreads();

        const float* a_sm = As[buf];
        const float* b_sm = Bs[buf];

        #pragma unroll
        for (int ks = 0; ks < 2; ks++) {
            const int kb = ks * 8;
            uint32_t af[2][4], bf[8][2];
            #pragma unroll
            for (int mi = 0; mi < 2; mi++) {
                int r = (wm * 32 + mi * 16 + gid) * A_STRIDE + kb + tig;
                af[mi][0] = f2tf32(a_sm[r]);
                af[mi][1] = f2tf32(a_sm[r + 8 * A_STRIDE]);
                af[mi][2] = f2tf32(a_sm[r + 4]);
                af[mi][3] = f2tf32(a_sm[r + 8 * A_STRIDE + 4]);
            }
            #pragma unroll
            for (int ni = 0; ni < 8; ni++) {
                int c = (kb + tig) * B_STRIDE + wn * 64 + ni * 8 + gid;
                bf[ni][0] = f2tf32(b_sm[c]);
                bf[ni][1] = f2tf32(b_sm[c + 4 * B_STRIDE]);
            }
            #pragma unroll
            for (int mi = 0; mi < 2; mi++)
                #pragma unroll
                for (int ni = 0; ni < 8; ni++) {
                    asm volatile(
                        "mma.sync.aligned.m16n8k8.row.col.f32.tf32.tf32.f32 "
                        "{%0,%1,%2,%3}, {%4,%5,%6,%7}, {%8,%9}, {%0,%1,%2,%3};"
                        : "+f"(acc[mi][ni][0]), "+f"(acc[mi][ni][1]),
                          "+f"(acc[mi][ni][2]), "+f"(acc[mi][ni][3])
                        : "r"(af[mi][0]), "r"(af[mi][1]),
                          "r"(af[mi][2]), "r"(af[mi][3]),
                          "r"(bf[ni][0]), "r"(bf[ni][1]));
                }
        }
        __syncthreads();
        buf ^= 1;
    }

    // epilogue: fragment c0,c1 -> (row, 2*tig), (row, 2*tig+1); c2,c3 -> row+8
    #pragma unroll
    for (int mi = 0; mi < 2; mi++) {
        int r = m0 + wm * 32 + mi * 16 + gid;
        #pragma unroll
        for (int ni = 0; ni < 8; ni++) {
            int c = n0 + wn * 64 + ni * 8 + tig * 2;
            float2 v0 = make_float2(acc[mi][ni][0], acc[mi][ni][1]);
            float2 v1 = make_float2(acc[mi][ni][2], acc[mi][ni][3]);
            if (EPI == 1) {
                float bx0 = bias[c], bx1 = bias[c + 1];
                v0.x = fmaxf(v0.x + bx0, 0.f); v0.y = fmaxf(v0.y + bx1, 0.f);
                v1.x = fmaxf(v1.x + bx0, 0.f); v1.y = fmaxf(v1.y + bx1, 0.f);
            } else if (EPI == 2) {
                float bx0 = bias[c], bx1 = bias[c + 1];
                float2 r0v = *(const float2*)(add + (size_t)r * N + c);
                float2 r1v = *(const float2*)(add + (size_t)(r + 8) * N + c);
                v0.x += bx0 + r0v.x; v0.y += bx1 + r0v.y;
                v1.x += bx0 + r1v.x; v1.y += bx1 + r1v.y;
            }
            *(float2*)(C + (size_t)r * N + c)       = v0;
            *(float2*)(C + (size_t)(r + 8) * N + c) = v1;
        }
    }
}

// ---------------- Attention: one block per (batch, head) ----------------
#define ATTN_SMEM ((T_SEQ * 65 + T_SEQ * 64 + 8 * T_SEQ + 8 * HS) * 4)

__global__ void attn_kernel(const float* __restrict__ Q,
                            const float* __restrict__ K,
                            const float* __restrict__ V,
                            float* __restrict__ O)
{
    extern __shared__ float sm[];
    float* Ks  = sm;                       // T_SEQ * 65
    float* Vs  = Ks + T_SEQ * 65;          // T_SEQ * 64
    float* Ssc = Vs + T_SEQ * 64;          // 8 * T_SEQ
    float* Qs  = Ssc + 8 * T_SEQ;          // 8 * HS

    int bh = blockIdx.x;
    int b = bh / NH, h = bh % NH;
    int tid = threadIdx.x;

    const float* Kg = K + (size_t)(b * T_SEQ) * EMBD + h * HS;
    const float* Vg = V + (size_t)(b * T_SEQ) * EMBD + h * HS;
    for (int i = tid; i < T_SEQ * HS; i += blockDim.x) {
        int j = i >> 6, d = i & 63;
        Ks[j * 65 + d] = Kg[(size_t)j * EMBD + d];
        Vs[j * 64 + d] = Vg[(size_t)j * EMBD + d];
    }
    __syncthreads();

    int warp = tid >> 5, lane = tid & 31;
    float* myS = Ssc + warp * T_SEQ;
    float* myQ = Qs + warp * HS;
    const float scale = 0.05103103630798288f;   // 384^-0.5

    for (int t = warp; t < T_SEQ; t += 8) {
        const float* qrow = Q + (size_t)(b * T_SEQ + t) * EMBD + h * HS;
        myQ[lane]      = qrow[lane];
        myQ[lane + 32] = qrow[lane + 32];
        __syncwarp();

        for (int j = lane; j <= t; j += 32) {
            float s = 0.f;
            #pragma unroll
            for (int d = 0; d < HS; d++) s += myQ[d] * Ks[j * 65 + d];
            myS[j] = s * scale;
        }
        __syncwarp();

        float m = -1e30f;
        for (int j = lane; j <= t; j += 32) m = fmaxf(m, myS[j]);
        #pragma unroll
        for (int o = 16; o; o >>= 1) m = fmaxf(m, __shfl_xor_sync(0xffffffffu, m, o));

        float sum = 0.f;
        for (int j = lane; j <= t; j += 32) {
            float p = __expf(myS[j] - m);
            myS[j] = p;
            sum += p;
        }
        #pragma unroll
        for (int o = 16; o; o >>= 1) sum += __shfl_xor_sync(0xffffffffu, sum, o);
        __syncwarp();
        float inv = 1.f / sum;

        float a0 = 0.f, a1 = 0.f;
        for (int j = 0; j <= t; j++) {
            float p = myS[j];
            a0 += p * Vs[j * 64 + lane];
            a1 += p * Vs[j * 64 + lane + 32];
        }
        float* orow = O + (size_t)(b * T_SEQ + t) * EMBD + h * HS;
        orow[lane]      = a0 * inv;
        orow[lane + 32] = a1 * inv;
        __syncwarp();
    }
}

// ---------------- launch ----------------
extern "C" void kernel_launch(void* const* d_in, const int* in_sizes, int n_in,
                              void* d_out, int out_size)
{
    const float* x     = (const float*)d_in[0];
    const float* Wq    = (const float*)d_in[1];
    const float* Wk    = (const float*)d_in[2];
    const float* Wv    = (const float*)d_in[3];
    const float* Wproj = (const float*)d_in[4];
    const float* bproj = (const float*)d_in[5];
    const float* W1    = (const float*)d_in[6];
    const float* b1    = (const float*)d_in[7];
    const float* W2    = (const float*)d_in[8];
    const float* b2    = (const float*)d_in[9];
    const float* g1    = (const float*)d_in[10];
    const float* be1   = (const float*)d_in[11];
    const float* g2    = (const float*)d_in[12];
    const float* be2   = (const float*)d_in[13];

    float *H, *Q, *K, *V, *A, *X1, *F;
    cudaGetSymbolAddress((void**)&H,  g_H);
    cudaGetSymbolAddress((void**)&Q,  g_Q);
    cudaGetSymbolAddress((void**)&K,  g_K);
    cudaGetSymbolAddress((void**)&V,  g_V);
    cudaGetSymbolAddress((void**)&A,  g_A);
    cudaGetSymbolAddress((void**)&X1, g_X1);
    cudaGetSymbolAddress((void**)&F,  g_F);

    cudaFuncSetAttribute(attn_kernel,
                         cudaFuncAttributeMaxDynamicSharedMemorySize, ATTN_SMEM);

    dim3 blk(256);
    dim3 g384(EMBD / 128,  M_ROWS / 128);   // (3, 400)
    dim3 gffn(FFN_D / 128, M_ROWS / 128);   // (12, 400)

    // 1) h = LN(x)
    ln_kernel<<<M_ROWS, 128>>>(x, g1, be1, H);
    // 2) q,k,v = h @ W{q,k,v}
    gemm_tc<0><<<g384, blk>>>(H, Wq, nullptr, nullptr, Q, M_ROWS, EMBD, EMBD);
    gemm_tc<0><<<g384, blk>>>(H, Wk, nullptr, nullptr, K, M_ROWS, EMBD, EMBD);
    gemm_tc<0><<<g384, blk>>>(H, Wv, nullptr, nullptr, V, M_ROWS, EMBD, EMBD);
    // 3) att = softmax(causal(q k^T * scale)) v
    attn_kernel<<<BATCH * NH, blk, ATTN_SMEM>>>(Q, K, V, A);
    // 4) x1 = x + att @ Wproj + bproj
    gemm_tc<2><<<g384, blk>>>(A, Wproj, bproj, x, X1, M_ROWS, EMBD, EMBD);
    // 5) h2 = LN(x1)
    ln_kernel<<<M_ROWS, 128>>>(X1, g2, be2, H);
    // 6) f = relu(h2 @ W1 + b1)
    gemm_tc<1><<<gffn, blk>>>(H, W1, b1, nullptr, F, M_ROWS, FFN_D, EMBD);
    // 7) out = x1 + f @ W2 + b2
    gemm_tc<2><<<g384, blk>>>(F, W2, b2, X1, (float*)d_out, M_ROWS, EMBD, FFN_D);
}

// round 7
// speedup vs baseline: 2.7200x; 1.0663x over previous
#include <cuda_runtime.h>
#include <cstdint>

#define EMBD   384
#define FFN_D  1536
#define T_SEQ  200
#define NH     6
#define HS     64
#define BATCH  256
#define M_ROWS (BATCH * T_SEQ)   // 51200
#define LDQ    1152              // fused QKV row stride

// ---------------- scratch (no allocations allowed) ----------------
__device__ float g_H  [M_ROWS * EMBD];
__device__ float g_QKV[M_ROWS * LDQ];
__device__ float g_A  [M_ROWS * EMBD];
__device__ float g_X1 [M_ROWS * EMBD];
__device__ float g_F  [M_ROWS * FFN_D];
// transposed, k-permuted, tf32-rounded weight copies
__device__ float g_Wqkv[LDQ * EMBD];     // [1152][384]
__device__ float g_Wp  [EMBD * EMBD];    // [384][384]
__device__ float g_W1t [FFN_D * EMBD];   // [1536][384]
__device__ float g_W2t [EMBD * FFN_D];   // [384][1536]

// ---------------- helpers ----------------
__device__ __forceinline__ float rndtf32(float f) {
    uint32_t r;
    asm("cvt.rna.tf32.f32 %0, %1;" : "=r"(r) : "f"(f));
    return __uint_as_float(r);
}

__device__ __forceinline__ void cp16(void* dst_smem, const void* src) {
    uint32_t d = (uint32_t)__cvta_generic_to_shared(dst_smem);
    asm volatile("cp.async.cg.shared.global [%0], [%1], 16;" :: "r"(d), "l"(src));
}
#define CP_COMMIT()  asm volatile("cp.async.commit_group;")
#define CP_WAIT(n)   asm volatile("cp.async.wait_group %0;" :: "n"(n))

// ---------------- weight prep: round to tf32, transpose, k-permute ----------------
// src: W[K][N] row-major.  dst: Wt[N][Kphys] where within each 8-group
// kphys = (k&3)*2 + ((k>>2)&1)  so a thread's (k, k+4) mma pair is adjacent.
__global__ void prep_w(const float* __restrict__ src, float* __restrict__ dst,
                       int K, int N)
{
    int idx = blockIdx.x * 256 + threadIdx.x;
    if (idx >= K * N) return;
    int k = idx / N, n = idx - k * N;
    int kp = (k & ~7) | ((k & 3) << 1) | ((k >> 2) & 1);
    dst[(size_t)n * K + kp] = rndtf32(src[idx]);
}

// ---------------- LayerNorm (rounds output to tf32 for GEMM A-operand) ----------------
__global__ void ln_kernel(const float* __restrict__ x,
                          const float* __restrict__ g,
                          const float* __restrict__ be,
                          float* __restrict__ out)
{
    __shared__ float red[4];
    int row = blockIdx.x;
    int t = threadIdx.x;               // 128 threads, 3 elems each
    const float* xr = x + (size_t)row * EMBD;

    float v0 = xr[t], v1 = xr[t + 128], v2 = xr[t + 256];
    float s = v0 + v1 + v2;
    #pragma unroll
    for (int o = 16; o; o >>= 1) s += __shfl_xor_sync(0xffffffffu, s, o);
    if ((t & 31) == 0) red[t >> 5] = s;
    __syncthreads();
    float mean = (red[0] + red[1] + red[2] + red[3]) * (1.0f / EMBD);
    __syncthreads();

    float d0 = v0 - mean, d1 = v1 - mean, d2 = v2 - mean;
    float sq = d0 * d0 + d1 * d1 + d2 * d2;
    #pragma unroll
    for (int o = 16; o; o >>= 1) sq += __shfl_xor_sync(0xffffffffu, sq, o);
    if ((t & 31) == 0) red[t >> 5] = sq;
    __syncthreads();
    float var = (red[0] + red[1] + red[2] + red[3]) * (1.0f / EMBD);
    float inv = rsqrtf(var + 1e-5f);

    float* orow = out + (size_t)row * EMBD;
    orow[t]       = rndtf32(d0 * inv * g[t]       + be[t]);
    orow[t + 128] = rndtf32(d1 * inv * g[t + 128] + be[t + 128]);
    orow[t + 256] = rndtf32(d2 * inv * g[t + 256] + be[t + 256]);
}

// ---------------- TF32 tensor-core GEMM ----------------
// C(M,N) = A(M,K) @ B(K,N), B passed pre-transposed/permuted as Bt[N][Kphys].
// All inputs pre-rounded to tf32 -> no cvt in the inner loop.
// EPI: 0 none, 1 bias+relu (rounds output), 2 bias+residual add.
// CTA 128x128, BK=16, 8 warps (4Mx2N), warp 32x64 = 2x8 m16n8k8 tiles.
#define A_STRIDE 20   // LDS.32 af: gid*20+tig covers all 32 banks
#define B_STRIDE 24   // LDS.64 bf: per half-warp gid*24+tig*2(+1) covers 32 banks

template <int EPI>
__global__ void __launch_bounds__(256)
gemm_tc(const float* __restrict__ A,
        const float* __restrict__ Bt,
        const float* __restrict__ bias,
        const float* __restrict__ add,
        float* __restrict__ C,
        int M, int N, int K)
{
    __shared__ float As[2][128 * A_STRIDE];
    __shared__ float Bs[2][128 * B_STRIDE];

    const int tid  = threadIdx.x;
    const int warp = tid >> 5, lane = tid & 31;
    const int wm   = warp >> 1, wn = warp & 1;
    const int gid  = lane >> 2, tig = lane & 3;
    const int m0   = blockIdx.y * 128, n0 = blockIdx.x * 128;

    const int am = tid >> 2, ak = (tid & 3) * 4;   // A: rows am, am+64
    const int bn = tid >> 1, bk = (tid & 1) * 4;   // B: row bn, k-chunks bk, bk+8

    float acc[2][8][4];
    #pragma unroll
    for (int i = 0; i < 2; i++)
        #pragma unroll
        for (int j = 0; j < 8; j++)
            #pragma unroll
            for (int l = 0; l < 4; l++) acc[i][j][l] = 0.f;

    const int nstages = K / 16;

    auto load_stage = [&](int buf, int k0) {
        cp16(&As[buf][am * A_STRIDE + ak],
             A + (size_t)(m0 + am) * K + k0 + ak);
        cp16(&As[buf][(am + 64) * A_STRIDE + ak],
             A + (size_t)(m0 + am + 64) * K + k0 + ak);
        cp16(&Bs[buf][bn * B_STRIDE + bk],
             Bt + (size_t)(n0 + bn) * K + k0 + bk);
        cp16(&Bs[buf][bn * B_STRIDE + bk + 8],
             Bt + (size_t)(n0 + bn) * K + k0 + bk + 8);
        CP_COMMIT();
    };

    load_stage(0, 0);
    int buf = 0;

    for (int s = 0; s < nstages; s++) {
        if (s + 1 < nstages) {
            load_stage(buf ^ 1, (s + 1) * 16);
            CP_WAIT(1);
        } else {
            CP_WAIT(0);
        }
        __syncthreads();

        const float* a_sm = As[buf];
        const float* b_sm = Bs[buf];

        #pragma unroll
        for (int ks = 0; ks < 2; ks++) {
            const int kb = ks * 8;
            uint32_t af[2][4], bf[8][2];
            #pragma unroll
            for (int mi = 0; mi < 2; mi++) {
                const float* ap = &a_sm[(wm * 32 + mi * 16 + gid) * A_STRIDE + kb + tig];
                af[mi][0] = __float_as_uint(ap[0]);
                af[mi][1] = __float_as_uint(ap[8 * A_STRIDE]);
                af[mi][2] = __float_as_uint(ap[4]);
                af[mi][3] = __float_as_uint(ap[8 * A_STRIDE + 4]);
            }
            #pragma unroll
            for (int ni = 0; ni < 8; ni++) {
                float2 b2v = *(const float2*)
                    &b_sm[(wn * 64 + ni * 8 + gid) * B_STRIDE + kb + tig * 2];
                bf[ni][0] = __float_as_uint(b2v.x);
                bf[ni][1] = __float_as_uint(b2v.y);
            }
            #pragma unroll
            for (int mi = 0; mi < 2; mi++)
                #pragma unroll
                for (int ni = 0; ni < 8; ni++) {
                    asm volatile(
                        "mma.sync.aligned.m16n8k8.row.col.f32.tf32.tf32.f32 "
                        "{%0,%1,%2,%3}, {%4,%5,%6,%7}, {%8,%9}, {%0,%1,%2,%3};"
                        : "+f"(acc[mi][ni][0]), "+f"(acc[mi][ni][1]),
                          "+f"(acc[mi][ni][2]), "+f"(acc[mi][ni][3])
                        : "r"(af[mi][0]), "r"(af[mi][1]),
                          "r"(af[mi][2]), "r"(af[mi][3]),
                          "r"(bf[ni][0]), "r"(bf[ni][1]));
                }
        }
        __syncthreads();
        buf ^= 1;
    }

    #pragma unroll
    for (int mi = 0; mi < 2; mi++) {
        int r = m0 + wm * 32 + mi * 16 + gid;
        #pragma unroll
        for (int ni = 0; ni < 8; ni++) {
            int c = n0 + wn * 64 + ni * 8 + tig * 2;
            float2 v0 = make_float2(acc[mi][ni][0], acc[mi][ni][1]);
            float2 v1 = make_float2(acc[mi][ni][2], acc[mi][ni][3]);
            if (EPI == 1) {
                float bx0 = bias[c], bx1 = bias[c + 1];
                v0.x = rndtf32(fmaxf(v0.x + bx0, 0.f));
                v0.y = rndtf32(fmaxf(v0.y + bx1, 0.f));
                v1.x = rndtf32(fmaxf(v1.x + bx0, 0.f));
                v1.y = rndtf32(fmaxf(v1.y + bx1, 0.f));
            } else if (EPI == 2) {
                float bx0 = bias[c], bx1 = bias[c + 1];
                float2 r0v = *(const float2*)(add + (size_t)r * N + c);
                float2 r1v = *(const float2*)(add + (size_t)(r + 8) * N + c);
                v0.x += bx0 + r0v.x; v0.y += bx1 + r0v.y;
                v1.x += bx0 + r1v.x; v1.y += bx1 + r1v.y;
            }
            *(float2*)(C + (size_t)r * N + c)       = v0;
            *(float2*)(C + (size_t)(r + 8) * N + c) = v1;
        }
    }
}

// ---------------- Attention ----------------
// One block per (batch, head). Reads fused QKV (stride 1152).
// K in SMEM [j][d] (stride 68, float4 reads), V transposed [d][j] (stride 204,
// float4 reads along j). Scores live in registers (7 per lane per row).
// Each warp processes a PAIR (t, t+1) so every K/V byte is used twice.
#define VT_STRIDE 204
#define ATTN_SMEM ((T_SEQ * 68 + HS * VT_STRIDE + 8 * 2 * HS) * 4)

__global__ void attn_kernel(const float* __restrict__ QKV, float* __restrict__ O)
{
    extern __shared__ float sm[];
    float* Ks = sm;                          // 200 * 68
    float* Vt = Ks + T_SEQ * 68;             // 64 * 204
    float* Qs = Vt + HS * VT_STRIDE;         // 8 warps * 2 rows * 64

    int bh = blockIdx.x;
    int b = bh / NH, h = bh % NH;
    int tid = threadIdx.x, warp = tid >> 5, lane = tid & 31;

    const float* base = QKV + (size_t)b * T_SEQ * LDQ + h * HS;

    for (int i = tid; i < T_SEQ * HS; i += 256) {
        int j = i >> 6, d = i & 63;
        Ks[j * 68 + d]        = base[(size_t)j * LDQ + EMBD + d];
        Vt[d * VT_STRIDE + j] = base[(size_t)j * LDQ + 2 * EMBD + d];
    }
    // zero the Vt tail columns (200..203) so float4 tails never touch NaN garbage
    for (int i = tid; i < HS * 4; i += 256) {
        int d = i >> 2, c = i & 3;
        Vt[d * VT_STRIDE + T_SEQ + c] = 0.f;
    }
    __syncthreads();

    const float scale = 0.05103103630798288f;   // 384^-0.5
    float* q0 = Qs + warp * 128;
    float* q1 = q0 + 64;

    for (int t0 = warp * 2; t0 < T_SEQ; t0 += 16) {
        int t1 = t0 + 1;
        q0[lane]      = base[(size_t)t0 * LDQ + lane];
        q0[lane + 32] = base[(size_t)t0 * LDQ + lane + 32];
        q1[lane]      = base[(size_t)t1 * LDQ + lane];
        q1[lane + 32] = base[(size_t)t1 * LDQ + lane + 32];
        __syncwarp();

        float s0[7], s1[7];
        #pragma unroll
        for (int c = 0; c < 7; c++) { s0[c] = -1e30f; s1[c] = -1e30f; }

        #pragma unroll
        for (int c = 0; c < 7; c++) {
            int j = c * 32 + lane;
            if (j <= t1) {
                float acc0 = 0.f, acc1 = 0.f;
                #pragma unroll
                for (int dc = 0; dc < 16; dc++) {
                    float4 kv = *(const float4*)&Ks[j * 68 + dc * 4];
                    float4 qa = *(const float4*)&q0[dc * 4];
                    float4 qb = *(const float4*)&q1[dc * 4];
                    acc0 += kv.x * qa.x + kv.y * qa.y + kv.z * qa.z + kv.w * qa.w;
                    acc1 += kv.x * qb.x + kv.y * qb.y + kv.z * qb.z + kv.w * qb.w;
                }
                if (j <= t0) s0[c] = acc0 * scale;
                s1[c] = acc1 * scale;
            }
        }

        float m0 = -1e30f, m1 = -1e30f;
        #pragma unroll
        for (int c = 0; c < 7; c++) { m0 = fmaxf(m0, s0[c]); m1 = fmaxf(m1, s1[c]); }
        #pragma unroll
        for (int o = 16; o; o >>= 1) {
            m0 = fmaxf(m0, __shfl_xor_sync(0xffffffffu, m0, o));
            m1 = fmaxf(m1, __shfl_xor_sync(0xffffffffu, m1, o));
        }
        float sum0 = 0.f, sum1 = 0.f;
        #pragma unroll
        for (int c = 0; c < 7; c++) {
            s0[c] = __expf(s0[c] - m0); sum0 += s0[c];
            s1[c] = __expf(s1[c] - m1); sum1 += s1[c];
        }
        #pragma unroll
        for (int o = 16; o; o >>= 1) {
            sum0 += __shfl_xor_sync(0xffffffffu, sum0, o);
            sum1 += __shfl_xor_sync(0xffffffffu, sum1, o);
        }
        float inv0 = 1.f / sum0, inv1 = 1.f / sum1;

        float a0 = 0.f, a1 = 0.f, c0 = 0.f, c1 = 0.f;
        #pragma unroll
        for (int c = 0; c < 7; c++) {
            int jbase = c * 32;
            if (jbase > t1) break;
            float pa = s0[c], pb = s1[c];
            int jmax = t1 - jbase; if (jmax > 31) jmax = 31;
            for (int jj = 0; jj <= jmax; jj += 4) {
                float4 v0 = *(const float4*)&Vt[lane * VT_STRIDE + jbase + jj];
                float4 v1 = *(const float4*)&Vt[(lane + 32) * VT_STRIDE + jbase + jj];
                float pa0 = __shfl_sync(0xffffffffu, pa, jj);
                float pa1 = __shfl_sync(0xffffffffu, pa, jj + 1);
                float pa2 = __shfl_sync(0xffffffffu, pa, jj + 2);
                float pa3 = __shfl_sync(0xffffffffu, pa, jj + 3);
                float pb0 = __shfl_sync(0xffffffffu, pb, jj);
                float pb1 = __shfl_sync(0xffffffffu, pb, jj + 1);
                float pb2 = __shfl_sync(0xffffffffu, pb, jj + 2);
                float pb3 = __shfl_sync(0xffffffffu, pb, jj + 3);
                a0 += pa0 * v0.x + pa1 * v0.y + pa2 * v0.z + pa3 * v0.w;
                a1 += pa0 * v1.x + pa1 * v1.y + pa2 * v1.z + pa3 * v1.w;
                c0 += pb0 * v0.x + pb1 * v0.y + pb2 * v0.z + pb3 * v0.w;
                c1 += pb0 * v1.x + pb1 * v1.y + pb2 * v1.z + pb3 * v1.w;
            }
        }

        float* o0 = O + (size_t)(b * T_SEQ + t0) * EMBD + h * HS;
        float* o1 = o0 + EMBD;
        o0[lane]      = rndtf32(a0 * inv0);
        o0[lane + 32] = rndtf32(a1 * inv0);
        o1[lane]      = rndtf32(c0 * inv1);
        o1[lane + 32] = rndtf32(c1 * inv1);
        __syncwarp();
    }
}

// ---------------- launch ----------------
extern "C" void kernel_launch(void* const* d_in, const int* in_sizes, int n_in,
                              void* d_out, int out_size)
{
    const float* x     = (const float*)d_in[0];
    const float* Wq    = (const float*)d_in[1];
    const float* Wk    = (const float*)d_in[2];
    const float* Wv    = (const float*)d_in[3];
    const float* Wproj = (const float*)d_in[4];
    const float* bproj = (const float*)d_in[5];
    const float* W1    = (const float*)d_in[6];
    const float* b1    = (const float*)d_in[7];
    const float* W2    = (const float*)d_in[8];
    const float* b2    = (const float*)d_in[9];
    const float* g1    = (const float*)d_in[10];
    const float* be1   = (const float*)d_in[11];
    const float* g2    = (const float*)d_in[12];
    const float* be2   = (const float*)d_in[13];

    float *H, *QKV, *A, *X1, *F, *Wqkvt, *Wpt, *W1t, *W2t;
    cudaGetSymbolAddress((void**)&H,     g_H);
    cudaGetSymbolAddress((void**)&QKV,   g_QKV);
    cudaGetSymbolAddress((void**)&A,     g_A);
    cudaGetSymbolAddress((void**)&X1,    g_X1);
    cudaGetSymbolAddress((void**)&F,     g_F);
    cudaGetSymbolAddress((void**)&Wqkvt, g_Wqkv);
    cudaGetSymbolAddress((void**)&Wpt,   g_Wp);
    cudaGetSymbolAddress((void**)&W1t,   g_W1t);
    cudaGetSymbolAddress((void**)&W2t,   g_W2t);

    cudaFuncSetAttribute(attn_kernel,
                         cudaFuncAttributeMaxDynamicSharedMemorySize, ATTN_SMEM);

    dim3 blk(256);
    const int nW = (EMBD * EMBD + 255) / 256;
    const int nF = (EMBD * FFN_D + 255) / 256;

    // 0) weight prep: round/transpose/k-permute (runs every launch; deterministic)
    prep_w<<<nW, 256>>>(Wq,    Wqkvt,                      EMBD, EMBD);
    prep_w<<<nW, 256>>>(Wk,    Wqkvt + EMBD * EMBD,        EMBD, EMBD);
    prep_w<<<nW, 256>>>(Wv,    Wqkvt + 2 * EMBD * EMBD,    EMBD, EMBD);
    prep_w<<<nW, 256>>>(Wproj, Wpt,                        EMBD, EMBD);
    prep_w<<<nF, 256>>>(W1,    W1t,                        EMBD, FFN_D);
    prep_w<<<nF, 256>>>(W2,    W2t,                        FFN_D, EMBD);

    // 1) h = LN(x)   (tf32-rounded)
    ln_kernel<<<M_ROWS, 128>>>(x, g1, be1, H);
    // 2) qkv = h @ [Wq|Wk|Wv]  (fused, N=1152)
    gemm_tc<0><<<dim3(LDQ / 128, M_ROWS / 128), blk>>>(H, Wqkvt, nullptr, nullptr,
                                                       QKV, M_ROWS, LDQ, EMBD);
    // 3) att = softmax(causal(q k^T * scale)) v   (output tf32-rounded)
    attn_kernel<<<BATCH * NH, blk, ATTN_SMEM>>>(QKV, A);
    // 4) x1 = x + att @ Wproj + bproj
    gemm_tc<2><<<dim3(EMBD / 128, M_ROWS / 128), blk>>>(A, Wpt, bproj, x,
                                                        X1, M_ROWS, EMBD, EMBD);
    // 5) h2 = LN(x1)
    ln_kernel<<<M_ROWS, 128>>>(X1, g2, be2, H);
    // 6) f = relu(h2 @ W1 + b1)   (tf32-rounded)
    gemm_tc<1><<<dim3(FFN_D / 128, M_ROWS / 128), blk>>>(H, W1t, b1, nullptr,
                                                         F, M_ROWS, FFN_D, EMBD);
    // 7) out = x1 + f @ W2 + b2
    gemm_tc<2><<<dim3(EMBD / 128, M_ROWS / 128), blk>>>(F, W2t, b2, X1,
                                                        (float*)d_out, M_ROWS, EMBD, FFN_D);
}

// round 9
// speedup vs baseline: 3.4213x; 1.2578x over previous
#include <cuda_runtime.h>
#include <cuda_fp16.h>
#include <cstdint>

#define EMBD   384
#define FFN_D  1536
#define T_SEQ  200
#define NH     6
#define HS     64
#define BATCH  256
#define M_ROWS (BATCH * T_SEQ)   // 51200
#define LDQ    1152              // fused QKV row stride

// ---------------- scratch (no allocations allowed) ----------------
__device__ __half g_H [M_ROWS * EMBD];     // LN out, fp16 permuted
__device__ float  g_QKV[M_ROWS * LDQ];     // fp32 natural
__device__ __half g_A [M_ROWS * EMBD];     // attn out, fp16 permuted
__device__ float  g_X1[M_ROWS * EMBD];     // fp32 natural
__device__ __half g_F [M_ROWS * FFN_D];    // relu out, fp16 permuted
// fp16 weights: Wt[N][K], k pair-permuted + chunk-swizzled
__device__ __half g_Wqkv[LDQ * EMBD];
__device__ __half g_Wp  [EMBD * EMBD];
__device__ __half g_W1t [FFN_D * EMBD];
__device__ __half g_W2t [EMBD * FFN_D];

// ---------------- permuted fp16 layout ----------------
// Within each 16-feature block of row m:
//   pair p = (k&15)>>1 -> pp = (p&3)*2 + (p>>2)  (thread's pairs tig,tig+4 adjacent)
//   half h = pp*2 + (k&1); 8-byte chunk c = (h>>2) ^ (m&3)  (bank swizzle)
__device__ __forceinline__ int poff(int m, int k) {
    int b = k & 15;
    int p = b >> 1, o = b & 1;
    int pp = ((p & 3) << 1) | (p >> 2);
    int h = (pp << 1) | o;
    int c = (h >> 2) ^ (m & 3);
    return (k & ~15) | (c << 2) | (h & 3);
}

// ---------------- helpers ----------------
__device__ __forceinline__ uint32_t smem_u32(const void* p) {
    uint32_t a;
    asm("{ .reg .u64 t; cvta.to.shared.u64 t, %1; cvt.u32.u64 %0, t; }"
        : "=r"(a) : "l"(p));
    return a;
}
__device__ __forceinline__ void cp16(uint32_t dst, const void* src) {
    asm volatile("cp.async.cg.shared.global [%0], [%1], 16;" :: "r"(dst), "l"(src));
}
#define CP_COMMIT()  asm volatile("cp.async.commit_group;")
#define CP_WAIT(n)   asm volatile("cp.async.wait_group %0;" :: "n"(n))

// ---------------- weight prep: fp16, transpose, permute+swizzle ----------------
__global__ void prep_w(const float* __restrict__ src, __half* __restrict__ dst,
                       int K, int N)
{
    int idx = blockIdx.x * 256 + threadIdx.x;
    if (idx >= K * N) return;
    int k = idx / N, n = idx - k * N;
    dst[(size_t)n * K + poff(n, k)] = __float2half(src[idx]);
}

// ---------------- LayerNorm -> fp16 permuted ----------------
__global__ void ln_kernel(const float* __restrict__ x,
                          const float* __restrict__ g,
                          const float* __restrict__ be,
                          __half* __restrict__ out)
{
    __shared__ float red[4];
    int row = blockIdx.x;
    int t = threadIdx.x;
    const float* xr = x + (size_t)row * EMBD;

    float v0 = xr[t], v1 = xr[t + 128], v2 = xr[t + 256];
    float s = v0 + v1 + v2;
    #pragma unroll
    for (int o = 16; o; o >>= 1) s += __shfl_xor_sync(0xffffffffu, s, o);
    if ((t & 31) == 0) red[t >> 5] = s;
    __syncthreads();
    float mean = (red[0] + red[1] + red[2] + red[3]) * (1.0f / EMBD);
    __syncthreads();

    float d0 = v0 - mean, d1 = v1 - mean, d2 = v2 - mean;
    float sq = d0 * d0 + d1 * d1 + d2 * d2;
    #pragma unroll
    for (int o = 16; o; o >>= 1) sq += __shfl_xor_sync(0xffffffffu, sq, o);
    if ((t & 31) == 0) red[t >> 5] = sq;
    __syncthreads();
    float var = (red[0] + red[1] + red[2] + red[3]) * (1.0f / EMBD);
    float inv = rsqrtf(var + 1e-5f);

    __half* orow = out + (size_t)row * EMBD;
    orow[poff(row, t)]       = __float2half(d0 * inv * g[t]       + be[t]);
    orow[poff(row, t + 128)] = __float2half(d1 * inv * g[t + 128] + be[t + 128]);
    orow[poff(row, t + 256)] = __float2half(d2 * inv * g[t + 256] + be[t + 256]);
}

// ---------------- fp16 tensor-core GEMM ----------------
// C(M,N) = A(M,K) @ Bt(N,K)^T.  A, Bt fp16 in permuted/swizzled layout.
// EPI: 0 = none (fp32 natural out), 1 = bias+relu (fp16 permuted out),
//      2 = bias+residual (fp32 natural out).
// CTA 128x128, BK=32, 8 warps (4Mx2N), warp 32x64 = 2x8 m16n8k16 tiles.
// 3-stage cp.async pipeline, 16KB/stage.
template <int EPI>
__global__ void __launch_bounds__(256)
gemm_h(const __half* __restrict__ A,
       const __half* __restrict__ Bt,
       const float* __restrict__ bias,
       const float* __restrict__ add,
       void* __restrict__ Cv,
       int M, int N, int K)
{
    __shared__ __half As[3][128 * 32];
    __shared__ __half Bs[3][128 * 32];

    const int tid  = threadIdx.x;
    const int warp = tid >> 5, lane = tid & 31;
    const int wm   = warp >> 1, wn = warp & 1;
    const int gid  = lane >> 2, tig = lane & 3;
    const int m0   = blockIdx.y * 128, n0 = blockIdx.x * 128;

    const int lr = tid >> 1;           // load row 0..127
    const int lc = (tid & 1) * 32;     // byte offset within 64B row

    const char* Ag = (const char*)(A + (size_t)(m0 + lr) * K) + lc;
    const char* Bg = (const char*)(Bt + (size_t)(n0 + lr) * K) + lc;
    const uint32_t asm0 = smem_u32(&As[0][0]) + lr * 64 + lc;
    const uint32_t bsm0 = smem_u32(&Bs[0][0]) + lr * 64 + lc;

    float acc[2][8][4];
    #pragma unroll
    for (int i = 0; i < 2; i++)
        #pragma unroll
        for (int j = 0; j < 8; j++)
            #pragma unroll
            for (int l = 0; l < 4; l++) acc[i][j][l] = 0.f;

    const int S = K / 32;

    auto load_stage = [&](int buf, int k0) {
        const char* a = Ag + (size_t)k0 * 2;
        const char* b = Bg + (size_t)k0 * 2;
        uint32_t da = asm0 + buf * 8192, db = bsm0 + buf * 8192;
        cp16(da, a); cp16(da + 16, a + 16);
        cp16(db, b); cp16(db + 16, b + 16);
        CP_COMMIT();
    };

    load_stage(0, 0);
    if (S > 1) load_stage(1, 32); else CP_COMMIT();

    const int cx = ((tig ^ (gid & 3)) << 3);       // swizzled 8B chunk offset
    const char* asb = (const char*)&As[0][0];
    const char* bsb = (const char*)&Bs[0][0];

    for (int s = 0; s < S; s++) {
        int cur = s % 3;
        if (s + 2 < S) load_stage((s + 2) % 3, (s + 2) * 32);
        else           CP_COMMIT();
        CP_WAIT(2);
        __syncthreads();

        const char* a_sm = asb + cur * 8192;
        const char* b_sm = bsb + cur * 8192;

        #pragma unroll
        for (int blk = 0; blk < 2; blk++) {
            const int bo = blk * 32 + cx;
            uint2 af[2][2];
            #pragma unroll
            for (int mi = 0; mi < 2; mi++) {
                int base = (wm * 32 + mi * 16 + gid) * 64 + bo;
                af[mi][0] = *(const uint2*)(a_sm + base);            // a0, a2
                af[mi][1] = *(const uint2*)(a_sm + base + 8 * 64);   // a1, a3
            }
            uint2 bf[8];
            #pragma unroll
            for (int ni = 0; ni < 8; ni++)
                bf[ni] = *(const uint2*)(b_sm + (wn * 64 + ni * 8 + gid) * 64 + bo);

            #pragma unroll
            for (int mi = 0; mi < 2; mi++)
                #pragma unroll
                for (int ni = 0; ni < 8; ni++) {
                    asm volatile(
                        "mma.sync.aligned.m16n8k16.row.col.f32.f16.f16.f32 "
                        "{%0,%1,%2,%3}, {%4,%5,%6,%7}, {%8,%9}, {%0,%1,%2,%3};"
                        : "+f"(acc[mi][ni][0]), "+f"(acc[mi][ni][1]),
                          "+f"(acc[mi][ni][2]), "+f"(acc[mi][ni][3])
                        : "r"(af[mi][0].x), "r"(af[mi][1].x),
                          "r"(af[mi][0].y), "r"(af[mi][1].y),
                          "r"(bf[ni].x),    "r"(bf[ni].y));
                }
        }
        __syncthreads();
    }

    // ---------------- epilogue ----------------
    #pragma unroll
    for (int mi = 0; mi < 2; mi++) {
        int r = m0 + wm * 32 + mi * 16 + gid;
        #pragma unroll
        for (int ni = 0; ni < 8; ni++) {
            int c = n0 + wn * 64 + ni * 8 + tig * 2;
            float v00 = acc[mi][ni][0], v01 = acc[mi][ni][1];
            float v10 = acc[mi][ni][2], v11 = acc[mi][ni][3];
            if (EPI == 1) {
                // bias + relu -> fp16 permuted layout
                float bx0 = bias[c], bx1 = bias[c + 1];
                v00 = fmaxf(v00 + bx0, 0.f); v01 = fmaxf(v01 + bx1, 0.f);
                v10 = fmaxf(v10 + bx0, 0.f); v11 = fmaxf(v11 + bx1, 0.f);
                __half* Ch = (__half*)Cv;
                int bb = c & 15, p = bb >> 1;
                int pp = ((p & 3) << 1) | (p >> 2);
                int h = pp << 1;
                int ch = (h >> 2) ^ (r & 3);           // (r+8)&3 == r&3
                int off = (c & ~15) | (ch << 2) | (h & 3);
                *(half2*)(Ch + (size_t)r * N + off)       = __floats2half2_rn(v00, v01);
                *(half2*)(Ch + (size_t)(r + 8) * N + off) = __floats2half2_rn(v10, v11);
            } else {
                float* Cf = (float*)Cv;
                if (EPI == 2) {
                    float bx0 = bias[c], bx1 = bias[c + 1];
                    float2 r0v = *(const float2*)(add + (size_t)r * N + c);
                    float2 r1v = *(const float2*)(add + (size_t)(r + 8) * N + c);
                    v00 += bx0 + r0v.x; v01 += bx1 + r0v.y;
                    v10 += bx0 + r1v.x; v11 += bx1 + r1v.y;
                }
                *(float2*)(Cf + (size_t)r * N + c)       = make_float2(v00, v01);
                *(float2*)(Cf + (size_t)(r + 8) * N + c) = make_float2(v10, v11);
            }
        }
    }
}

// ---------------- Attention (fp32 in, fp16-permuted out) ----------------
#define VT_STRIDE 204
#define ATTN_SMEM ((T_SEQ * 68 + HS * VT_STRIDE + 8 * 2 * HS) * 4)

__global__ void attn_kernel(const float* __restrict__ QKV, __half* __restrict__ O)
{
    extern __shared__ float sm[];
    float* Ks = sm;
    float* Vt = Ks + T_SEQ * 68;
    float* Qs = Vt + HS * VT_STRIDE;

    int bh = blockIdx.x;
    int b = bh / NH, h = bh % NH;
    int tid = threadIdx.x, warp = tid >> 5, lane = tid & 31;

    const float* base = QKV + (size_t)b * T_SEQ * LDQ + h * HS;

    for (int i = tid; i < T_SEQ * HS; i += 256) {
        int j = i >> 6, d = i & 63;
        Ks[j * 68 + d]        = base[(size_t)j * LDQ + EMBD + d];
        Vt[d * VT_STRIDE + j] = base[(size_t)j * LDQ + 2 * EMBD + d];
    }
    for (int i = tid; i < HS * 4; i += 256) {
        int d = i >> 2, c = i & 3;
        Vt[d * VT_STRIDE + T_SEQ + c] = 0.f;
    }
    __syncthreads();

    const float scale = 0.05103103630798288f;   // 384^-0.5
    float* q0 = Qs + warp * 128;
    float* q1 = q0 + 64;

    for (int t0 = warp * 2; t0 < T_SEQ; t0 += 16) {
        int t1 = t0 + 1;
        q0[lane]      = base[(size_t)t0 * LDQ + lane];
        q0[lane + 32] = base[(size_t)t0 * LDQ + lane + 32];
        q1[lane]      = base[(size_t)t1 * LDQ + lane];
        q1[lane + 32] = base[(size_t)t1 * LDQ + lane + 32];
        __syncwarp();

        float s0[7], s1[7];
        #pragma unroll
        for (int c = 0; c < 7; c++) { s0[c] = -1e30f; s1[c] = -1e30f; }

        #pragma unroll
        for (int c = 0; c < 7; c++) {
            int j = c * 32 + lane;
            if (j <= t1) {
                float acc0 = 0.f, acc1 = 0.f;
                #pragma unroll
                for (int dc = 0; dc < 16; dc++) {
                    float4 kv = *(const float4*)&Ks[j * 68 + dc * 4];
                    float4 qa = *(const float4*)&q0[dc * 4];
                    float4 qb = *(const float4*)&q1[dc * 4];
                    acc0 += kv.x * qa.x + kv.y * qa.y + kv.z * qa.z + kv.w * qa.w;
                    acc1 += kv.x * qb.x + kv.y * qb.y + kv.z * qb.z + kv.w * qb.w;
                }
                if (j <= t0) s0[c] = acc0 * scale;
                s1[c] = acc1 * scale;
            }
        }

        float m0 = -1e30f, m1 = -1e30f;
        #pragma unroll
        for (int c = 0; c < 7; c++) { m0 = fmaxf(m0, s0[c]); m1 = fmaxf(m1, s1[c]); }
        #pragma unroll
        for (int o = 16; o; o >>= 1) {
            m0 = fmaxf(m0, __shfl_xor_sync(0xffffffffu, m0, o));
            m1 = fmaxf(m1, __shfl_xor_sync(0xffffffffu, m1, o));
        }
        float sum0 = 0.f, sum1 = 0.f;
        #pragma unroll
        for (int c = 0; c < 7; c++) {
            s0[c] = __expf(s0[c] - m0); sum0 += s0[c];
            s1[c] = __expf(s1[c] - m1); sum1 += s1[c];
        }
        #pragma unroll
        for (int o = 16; o; o >>= 1) {
            sum0 += __shfl_xor_sync(0xffffffffu, sum0, o);
            sum1 += __shfl_xor_sync(0xffffffffu, sum1, o);
        }
        float inv0 = 1.f / sum0, inv1 = 1.f / sum1;

        float a0 = 0.f, a1 = 0.f, c0 = 0.f, c1 = 0.f;
        #pragma unroll
        for (int c = 0; c < 7; c++) {
            int jbase = c * 32;
            if (jbase > t1) break;
            float pa = s0[c], pb = s1[c];
            int jmax = t1 - jbase; if (jmax > 31) jmax = 31;
            for (int jj = 0; jj <= jmax; jj += 4) {
                float4 v0 = *(const float4*)&Vt[lane * VT_STRIDE + jbase + jj];
                float4 v1 = *(const float4*)&Vt[(lane + 32) * VT_STRIDE + jbase + jj];
                float pa0 = __shfl_sync(0xffffffffu, pa, jj);
                float pa1 = __shfl_sync(0xffffffffu, pa, jj + 1);
                float pa2 = __shfl_sync(0xffffffffu, pa, jj + 2);
                float pa3 = __shfl_sync(0xffffffffu, pa, jj + 3);
                float pb0 = __shfl_sync(0xffffffffu, pb, jj);
                float pb1 = __shfl_sync(0xffffffffu, pb, jj + 1);
                float pb2 = __shfl_sync(0xffffffffu, pb, jj + 2);
                float pb3 = __shfl_sync(0xffffffffu, pb, jj + 3);
                a0 += pa0 * v0.x + pa1 * v0.y + pa2 * v0.z + pa3 * v0.w;
                a1 += pa0 * v1.x + pa1 * v1.y + pa2 * v1.z + pa3 * v1.w;
                c0 += pb0 * v0.x + pb1 * v0.y + pb2 * v0.z + pb3 * v0.w;
                c1 += pb0 * v1.x + pb1 * v1.y + pb2 * v1.z + pb3 * v1.w;
            }
        }

        // write fp16 permuted (A-operand of proj GEMM)
        int mrow0 = b * T_SEQ + t0, mrow1 = mrow0 + 1;
        int f0 = h * HS + lane, f1 = f0 + 32;
        __half* o0 = O + (size_t)mrow0 * EMBD;
        __half* o1 = O + (size_t)mrow1 * EMBD;
        o0[poff(mrow0, f0)] = __float2half(a0 * inv0);
        o0[poff(mrow0, f1)] = __float2half(a1 * inv0);
        o1[poff(mrow1, f0)] = __float2half(c0 * inv1);
        o1[poff(mrow1, f1)] = __float2half(c1 * inv1);
        __syncwarp();
    }
}

// ---------------- launch ----------------
extern "C" void kernel_launch(void* const* d_in, const int* in_sizes, int n_in,
                              void* d_out, int out_size)
{
    const float* x     = (const float*)d_in[0];
    const float* Wq    = (const float*)d_in[1];
    const float* Wk    = (const float*)d_in[2];
    const float* Wv    = (const float*)d_in[3];
    const float* Wproj = (const float*)d_in[4];
    const float* bproj = (const float*)d_in[5];
    const float* W1    = (const float*)d_in[6];
    const float* b1    = (const float*)d_in[7];
    const float* W2    = (const float*)d_in[8];
    const float* b2    = (const float*)d_in[9];
    const float* g1    = (const float*)d_in[10];
    const float* be1   = (const float*)d_in[11];
    const float* g2    = (const float*)d_in[12];
    const float* be2   = (const float*)d_in[13];

    __half *H, *A, *F, *Wqkvt, *Wpt, *W1t, *W2t;
    float *QKV, *X1;
    cudaGetSymbolAddress((void**)&H,     g_H);
    cudaGetSymbolAddress((void**)&QKV,   g_QKV);
    cudaGetSymbolAddress((void**)&A,     g_A);
    cudaGetSymbolAddress((void**)&X1,    g_X1);
    cudaGetSymbolAddress((void**)&F,     g_F);
    cudaGetSymbolAddress((void**)&Wqkvt, g_Wqkv);
    cudaGetSymbolAddress((void**)&Wpt,   g_Wp);
    cudaGetSymbolAddress((void**)&W1t,   g_W1t);
    cudaGetSymbolAddress((void**)&W2t,   g_W2t);

    cudaFuncSetAttribute(attn_kernel,
                         cudaFuncAttributeMaxDynamicSharedMemorySize, ATTN_SMEM);

    dim3 blk(256);
    const int nW = (EMBD * EMBD + 255) / 256;
    const int nF = (EMBD * FFN_D + 255) / 256;

    // 0) weight prep: fp16 + transpose + permute/swizzle
    prep_w<<<nW, 256>>>(Wq,    Wqkvt,                   EMBD, EMBD);
    prep_w<<<nW, 256>>>(Wk,    Wqkvt + EMBD * EMBD,     EMBD, EMBD);
    prep_w<<<nW, 256>>>(Wv,    Wqkvt + 2 * EMBD * EMBD, EMBD, EMBD);
    prep_w<<<nW, 256>>>(Wproj, Wpt,                     EMBD, EMBD);
    prep_w<<<nF, 256>>>(W1,    W1t,                     EMBD, FFN_D);
    prep_w<<<nF, 256>>>(W2,    W2t,                     FFN_D, EMBD);

    // 1) h = LN(x)  -> fp16 permuted
    ln_kernel<<<M_ROWS, 128>>>(x, g1, be1, H);
    // 2) qkv = h @ [Wq|Wk|Wv]  -> fp32 natural
    gemm_h<0><<<dim3(LDQ / 128, M_ROWS / 128), blk>>>(
        H, Wqkvt, nullptr, nullptr, QKV, M_ROWS, LDQ, EMBD);
    // 3) attention -> fp16 permuted
    attn_kernel<<<BATCH * NH, blk, ATTN_SMEM>>>(QKV, A);
    // 4) x1 = x + att @ Wproj + bproj  -> fp32 natural
    gemm_h<2><<<dim3(EMBD / 128, M_ROWS / 128), blk>>>(
        A, Wpt, bproj, x, X1, M_ROWS, EMBD, EMBD);
    // 5) h2 = LN(x1) -> fp16 permuted
    ln_kernel<<<M_ROWS, 128>>>(X1, g2, be2, H);
    // 6) f = relu(h2 @ W1 + b1) -> fp16 permuted
    gemm_h<1><<<dim3(FFN_D / 128, M_ROWS / 128), blk>>>(
        H, W1t, b1, nullptr, F, M_ROWS, FFN_D, EMBD);
    // 7) out = x1 + f @ W2 + b2 -> fp32 natural
    gemm_h<2><<<dim3(EMBD / 128, M_ROWS / 128), blk>>>(
        F, W2t, b2, X1, (float*)d_out, M_ROWS, EMBD, FFN_D);
}

// round 10
// speedup vs baseline: 3.8617x; 1.1287x over previous
#include <cuda_runtime.h>
#include <cuda_fp16.h>
#include <cstdint>

#define EMBD   384
#define FFN_D  1536
#define T_SEQ  200
#define NH     6
#define HS     64
#define BATCH  256
#define M_ROWS (BATCH * T_SEQ)   // 51200
#define LDQ    1152              // fused QKV row stride

// ---------------- scratch (no allocations allowed) ----------------
__device__ __half g_H [M_ROWS * EMBD];     // LN out, fp16 permuted
__device__ float  g_QKV[M_ROWS * LDQ];     // fp32 natural
__device__ __half g_A [M_ROWS * EMBD];     // attn out, fp16 permuted
__device__ float  g_X1[M_ROWS * EMBD];     // fp32 natural
__device__ __half g_F [M_ROWS * FFN_D];    // relu out, fp16 permuted
// fp16 weights: Wt[N][K], k pair-permuted + chunk-swizzled
__device__ __half g_Wqkv[LDQ * EMBD];
__device__ __half g_Wp  [EMBD * EMBD];
__device__ __half g_W1t [FFN_D * EMBD];
__device__ __half g_W2t [EMBD * FFN_D];

// ---------------- permuted fp16 layout ----------------
// Within each 16-feature block of row m:
//   pair p = (k&15)>>1 -> pp = (p&3)*2 + (p>>2); half h = pp*2 + (k&1);
//   8-byte chunk c = (h>>2) ^ (m&3)  (bank swizzle)
__device__ __forceinline__ int poff(int m, int k) {
    int b = k & 15;
    int p = b >> 1, o = b & 1;
    int pp = ((p & 3) << 1) | (p >> 2);
    int h = (pp << 1) | o;
    int c = (h >> 2) ^ (m & 3);
    return (k & ~15) | (c << 2) | (h & 3);
}

// ---------------- helpers ----------------
__device__ __forceinline__ uint32_t smem_u32(const void* p) {
    uint32_t a;
    asm("{ .reg .u64 t; cvta.to.shared.u64 t, %1; cvt.u32.u64 %0, t; }"
        : "=r"(a) : "l"(p));
    return a;
}
__device__ __forceinline__ void cp16(uint32_t dst, const void* src) {
    asm volatile("cp.async.cg.shared.global [%0], [%1], 16;" :: "r"(dst), "l"(src));
}
#define CP_COMMIT()  asm volatile("cp.async.commit_group;")
#define CP_WAIT(n)   asm volatile("cp.async.wait_group %0;" :: "n"(n))

#define MMA16816(acc, a0, a1, a2, a3, b0, b1)                          \
    asm volatile(                                                      \
        "mma.sync.aligned.m16n8k16.row.col.f32.f16.f16.f32 "           \
        "{%0,%1,%2,%3}, {%4,%5,%6,%7}, {%8,%9}, {%0,%1,%2,%3};"        \
        : "+f"((acc)[0]), "+f"((acc)[1]), "+f"((acc)[2]), "+f"((acc)[3]) \
        : "r"(a0), "r"(a1), "r"(a2), "r"(a3), "r"(b0), "r"(b1))

// ---------------- weight prep ----------------
__global__ void prep_w(const float* __restrict__ src, __half* __restrict__ dst,
                       int K, int N)
{
    int idx = blockIdx.x * 256 + threadIdx.x;
    if (idx >= K * N) return;
    int k = idx / N, n = idx - k * N;
    dst[(size_t)n * K + poff(n, k)] = __float2half(src[idx]);
}

// ---------------- LayerNorm -> fp16 permuted ----------------
__global__ void ln_kernel(const float* __restrict__ x,
                          const float* __restrict__ g,
                          const float* __restrict__ be,
                          __half* __restrict__ out)
{
    __shared__ float red[4];
    int row = blockIdx.x;
    int t = threadIdx.x;
    const float* xr = x + (size_t)row * EMBD;

    float v0 = xr[t], v1 = xr[t + 128], v2 = xr[t + 256];
    float s = v0 + v1 + v2;
    #pragma unroll
    for (int o = 16; o; o >>= 1) s += __shfl_xor_sync(0xffffffffu, s, o);
    if ((t & 31) == 0) red[t >> 5] = s;
    __syncthreads();
    float mean = (red[0] + red[1] + red[2] + red[3]) * (1.0f / EMBD);
    __syncthreads();

    float d0 = v0 - mean, d1 = v1 - mean, d2 = v2 - mean;
    float sq = d0 * d0 + d1 * d1 + d2 * d2;
    #pragma unroll
    for (int o = 16; o; o >>= 1) sq += __shfl_xor_sync(0xffffffffu, sq, o);
    if ((t & 31) == 0) red[t >> 5] = sq;
    __syncthreads();
    float var = (red[0] + red[1] + red[2] + red[3]) * (1.0f / EMBD);
    float inv = rsqrtf(var + 1e-5f);

    __half* orow = out + (size_t)row * EMBD;
    orow[poff(row, t)]       = __float2half(d0 * inv * g[t]       + be[t]);
    orow[poff(row, t + 128)] = __float2half(d1 * inv * g[t + 128] + be[t + 128]);
    orow[poff(row, t + 256)] = __float2half(d2 * inv * g[t + 256] + be[t + 256]);
}

// ---------------- fp16 tensor-core GEMM (unchanged from R9) ----------------
template <int EPI>
__global__ void __launch_bounds__(256)
gemm_h(const __half* __restrict__ A,
       const __half* __restrict__ Bt,
       const float* __restrict__ bias,
       const float* __restrict__ add,
       void* __restrict__ Cv,
       int M, int N, int K)
{
    __shared__ __half As[3][128 * 32];
    __shared__ __half Bs[3][128 * 32];

    const int tid  = threadIdx.x;
    const int warp = tid >> 5, lane = tid & 31;
    const int wm   = warp >> 1, wn = warp & 1;
    const int gid  = lane >> 2, tig = lane & 3;
    const int m0   = blockIdx.y * 128, n0 = blockIdx.x * 128;

    const int lr = tid >> 1;
    const int lc = (tid & 1) * 32;

    const char* Ag = (const char*)(A + (size_t)(m0 + lr) * K) + lc;
    const char* Bg = (const char*)(Bt + (size_t)(n0 + lr) * K) + lc;
    const uint32_t asm0 = smem_u32(&As[0][0]) + lr * 64 + lc;
    const uint32_t bsm0 = smem_u32(&Bs[0][0]) + lr * 64 + lc;

    float acc[2][8][4];
    #pragma unroll
    for (int i = 0; i < 2; i++)
        #pragma unroll
        for (int j = 0; j < 8; j++)
            #pragma unroll
            for (int l = 0; l < 4; l++) acc[i][j][l] = 0.f;

    const int S = K / 32;

    auto load_stage = [&](int buf, int k0) {
        const char* a = Ag + (size_t)k0 * 2;
        const char* b = Bg + (size_t)k0 * 2;
        uint32_t da = asm0 + buf * 8192, db = bsm0 + buf * 8192;
        cp16(da, a); cp16(da + 16, a + 16);
        cp16(db, b); cp16(db + 16, b + 16);
        CP_COMMIT();
    };

    load_stage(0, 0);
    if (S > 1) load_stage(1, 32); else CP_COMMIT();

    const int cx = ((tig ^ (gid & 3)) << 3);
    const char* asb = (const char*)&As[0][0];
    const char* bsb = (const char*)&Bs[0][0];

    for (int s = 0; s < S; s++) {
        int cur = s % 3;
        if (s + 2 < S) load_stage((s + 2) % 3, (s + 2) * 32);
        else           CP_COMMIT();
        CP_WAIT(2);
        __syncthreads();

        const char* a_sm = asb + cur * 8192;
        const char* b_sm = bsb + cur * 8192;

        #pragma unroll
        for (int blk = 0; blk < 2; blk++) {
            const int bo = blk * 32 + cx;
            uint2 af[2][2];
            #pragma unroll
            for (int mi = 0; mi < 2; mi++) {
                int base = (wm * 32 + mi * 16 + gid) * 64 + bo;
                af[mi][0] = *(const uint2*)(a_sm + base);
                af[mi][1] = *(const uint2*)(a_sm + base + 8 * 64);
            }
            uint2 bf[8];
            #pragma unroll
            for (int ni = 0; ni < 8; ni++)
                bf[ni] = *(const uint2*)(b_sm + (wn * 64 + ni * 8 + gid) * 64 + bo);

            #pragma unroll
            for (int mi = 0; mi < 2; mi++)
                #pragma unroll
                for (int ni = 0; ni < 8; ni++)
                    MMA16816(acc[mi][ni],
                             af[mi][0].x, af[mi][1].x, af[mi][0].y, af[mi][1].y,
                             bf[ni].x, bf[ni].y);
        }
        __syncthreads();
    }

    #pragma unroll
    for (int mi = 0; mi < 2; mi++) {
        int r = m0 + wm * 32 + mi * 16 + gid;
        #pragma unroll
        for (int ni = 0; ni < 8; ni++) {
            int c = n0 + wn * 64 + ni * 8 + tig * 2;
            float v00 = acc[mi][ni][0], v01 = acc[mi][ni][1];
            float v10 = acc[mi][ni][2], v11 = acc[mi][ni][3];
            if (EPI == 1) {
                float bx0 = bias[c], bx1 = bias[c + 1];
                v00 = fmaxf(v00 + bx0, 0.f); v01 = fmaxf(v01 + bx1, 0.f);
                v10 = fmaxf(v10 + bx0, 0.f); v11 = fmaxf(v11 + bx1, 0.f);
                __half* Ch = (__half*)Cv;
                int off = poff(r, c);   // (r+8)&3 == r&3
                *(half2*)(Ch + (size_t)r * N + off)       = __floats2half2_rn(v00, v01);
                *(half2*)(Ch + (size_t)(r + 8) * N + off) = __floats2half2_rn(v10, v11);
            } else {
                float* Cf = (float*)Cv;
                if (EPI == 2) {
                    float bx0 = bias[c], bx1 = bias[c + 1];
                    float2 r0v = *(const float2*)(add + (size_t)r * N + c);
                    float2 r1v = *(const float2*)(add + (size_t)(r + 8) * N + c);
                    v00 += bx0 + r0v.x; v01 += bx1 + r0v.y;
                    v10 += bx0 + r1v.x; v11 += bx1 + r1v.y;
                }
                *(float2*)(Cf + (size_t)r * N + c)       = make_float2(v00, v01);
                *(float2*)(Cf + (size_t)(r + 8) * N + c) = make_float2(v10, v11);
            }
        }
    }
}

// ---------------- tensor-core attention ----------------
// Block = (q-tile of 64, b*NH+h). 8 warps: rg=warp>>1 (16 rows each), cg=warp&1
// (key-halves for S, d-halves for PV). All operands fp16 in the permuted layout.
#define KPAD 208
#define AT_K 4096                 // half offsets in dynamic smem
#define AT_V 16896
#define AT_P 30208
#define AT_RED 43520
#define ATTN2_SMEM (43520 * 2 + 1024)

__global__ void __launch_bounds__(256)
attn2(const float* __restrict__ QKV, __half* __restrict__ O)
{
    extern __shared__ __half sm2[];
    __half* Qs = sm2;                  // [64][64]
    __half* Ks = sm2 + AT_K;           // [200][64]  (row j, k d)
    __half* Vt = sm2 + AT_V;           // [64][208]  (row d, k j)
    __half* Ps = sm2 + AT_P;           // [64][208]  (row m, k j)
    float* redm = (float*)(sm2 + AT_RED);   // [2][64]
    float* reds = redm + 128;               // [2][64]

    const int qt = blockIdx.x, bh = blockIdx.y;
    const int b = bh / NH, h = bh % NH;
    const int q0 = qt * 64;
    const float* base = QKV + (size_t)b * T_SEQ * LDQ + h * HS;

    const int tid = threadIdx.x, warp = tid >> 5, lane = tid & 31;
    const int gid = lane >> 2, tig = lane & 3;
    const int rg = warp >> 1, cg = warp & 1;
    const int sw = ((tig ^ (gid & 3)) << 3);

    // ---- load Q tile, K, V(transposed) as fp16 permuted ----
    for (int i = tid; i < 64 * 64; i += 256) {
        int r = i >> 6, d = i & 63;
        int gq = q0 + r;
        float v = (gq < T_SEQ) ? base[(size_t)gq * LDQ + d] : 0.f;
        Qs[r * 64 + poff(r, d)] = __float2half(v);
    }
    for (int i = tid; i < T_SEQ * 64; i += 256) {
        int j = i >> 6, d = i & 63;
        Ks[j * 64 + poff(j, d)]   = __float2half(base[(size_t)j * LDQ + EMBD + d]);
        Vt[d * KPAD + poff(d, j)] = __float2half(base[(size_t)j * LDQ + 2 * EMBD + d]);
    }
    for (int i = tid; i < 64 * 8; i += 256) {
        int d = i >> 3, j = T_SEQ + (i & 7);
        Vt[d * KPAD + poff(d, j)] = __float2half(0.f);
    }
    __syncthreads();

    // ---- S = Q K^T (per-warp: 16 rows x 13/12 n-tiles) ----
    const int m0w = rg * 16;
    const int nt = cg ? 12 : 13;
    const char* qb = (const char*)Qs;
    const char* kbp = (const char*)Ks;
    char* pb = (char*)Ps;
    const char* vb = (const char*)Vt;

    float acc[13][4];
    #pragma unroll
    for (int ni = 0; ni < 13; ni++)
        #pragma unroll
        for (int l = 0; l < 4; l++) acc[ni][l] = 0.f;

    #pragma unroll
    for (int kb = 0; kb < 4; kb++) {
        uint2 a0 = *(const uint2*)(qb + (m0w + gid) * 128 + kb * 32 + sw);
        uint2 a1 = *(const uint2*)(qb + (m0w + gid + 8) * 128 + kb * 32 + sw);
        #pragma unroll
        for (int ni = 0; ni < 13; ni++) {
            if (ni < nt) {
                int jt = cg * 13 + ni;
                uint2 bf = *(const uint2*)(kbp + (jt * 8 + gid) * 128 + kb * 32 + sw);
                MMA16816(acc[ni], a0.x, a1.x, a0.y, a1.y, bf.x, bf.y);
            }
        }
    }

    // ---- causal mask + scale + row max (two rows per lane) ----
    const float scale = 0.05103103630798288f;   // 384^-0.5
    const int r0 = q0 + m0w + gid, r1 = r0 + 8;
    float mx0 = -1e30f, mx1 = -1e30f;
    #pragma unroll
    for (int ni = 0; ni < 13; ni++) {
        if (ni < nt) {
            int j0 = (cg * 13 + ni) * 8 + tig * 2;
            acc[ni][0] = (j0     <= r0) ? acc[ni][0] * scale : -1e30f;
            acc[ni][1] = (j0 + 1 <= r0) ? acc[ni][1] * scale : -1e30f;
            acc[ni][2] = (j0     <= r1) ? acc[ni][2] * scale : -1e30f;
            acc[ni][3] = (j0 + 1 <= r1) ? acc[ni][3] * scale : -1e30f;
            mx0 = fmaxf(mx0, fmaxf(acc[ni][0], acc[ni][1]));
            mx1 = fmaxf(mx1, fmaxf(acc[ni][2], acc[ni][3]));
        }
    }
    mx0 = fmaxf(mx0, __shfl_xor_sync(0xffffffffu, mx0, 1));
    mx0 = fmaxf(mx0, __shfl_xor_sync(0xffffffffu, mx0, 2));
    mx1 = fmaxf(mx1, __shfl_xor_sync(0xffffffffu, mx1, 1));
    mx1 = fmaxf(mx1, __shfl_xor_sync(0xffffffffu, mx1, 2));
    if (tig == 0) {
        redm[cg * 64 + m0w + gid]     = mx0;
        redm[cg * 64 + m0w + gid + 8] = mx1;
    }
    __syncthreads();
    mx0 = fmaxf(redm[m0w + gid],     redm[64 + m0w + gid]);
    mx1 = fmaxf(redm[m0w + gid + 8], redm[64 + m0w + gid + 8]);

    // ---- exp, partial sums, write P (fp16 permuted) ----
    float s0 = 0.f, s1 = 0.f;
    #pragma unroll
    for (int ni = 0; ni < 13; ni++) {
        if (ni < nt) {
            int j0 = (cg * 13 + ni) * 8 + tig * 2;
            float e00 = __expf(acc[ni][0] - mx0), e01 = __expf(acc[ni][1] - mx0);
            float e10 = __expf(acc[ni][2] - mx1), e11 = __expf(acc[ni][3] - mx1);
            s0 += e00 + e01; s1 += e10 + e11;
            int m_ = m0w + gid;
            *(half2*)(pb + m_ * 416 + poff(m_, j0) * 2) = __floats2half2_rn(e00, e01);
            m_ += 8;
            *(half2*)(pb + m_ * 416 + poff(m_, j0) * 2) = __floats2half2_rn(e10, e11);
        }
    }
    if (cg) {   // zero P tail cols [200,208)
        int j0 = T_SEQ + tig * 2;
        int m_ = m0w + gid;
        *(half2*)(pb + m_ * 416 + poff(m_, j0) * 2) = __floats2half2_rn(0.f, 0.f);
        m_ += 8;
        *(half2*)(pb + m_ * 416 + poff(m_, j0) * 2) = __floats2half2_rn(0.f, 0.f);
    }
    s0 += __shfl_xor_sync(0xffffffffu, s0, 1);
    s0 += __shfl_xor_sync(0xffffffffu, s0, 2);
    s1 += __shfl_xor_sync(0xffffffffu, s1, 1);
    s1 += __shfl_xor_sync(0xffffffffu, s1, 2);
    if (tig == 0) {
        reds[cg * 64 + m0w + gid]     = s0;
        reds[cg * 64 + m0w + gid + 8] = s1;
    }
    __syncthreads();

    // ---- O = P V (per-warp: 16 rows x 32 d-cols), divide by sum, store ----
    float oacc[4][4];
    #pragma unroll
    for (int ni = 0; ni < 4; ni++)
        #pragma unroll
        for (int l = 0; l < 4; l++) oacc[ni][l] = 0.f;

    #pragma unroll
    for (int kb = 0; kb < 13; kb++) {
        uint2 a0 = *(const uint2*)(pb + (m0w + gid) * 416 + kb * 32 + sw);
        uint2 a1 = *(const uint2*)(pb + (m0w + gid + 8) * 416 + kb * 32 + sw);
        #pragma unroll
        for (int ni = 0; ni < 4; ni++) {
            int d = cg * 32 + ni * 8 + gid;
            uint2 bf = *(const uint2*)(vb + d * 416 + kb * 32 + sw);
            MMA16816(oacc[ni], a0.x, a1.x, a0.y, a1.y, bf.x, bf.y);
        }
    }

    float inv0 = 1.f / (reds[m0w + gid]     + reds[64 + m0w + gid]);
    float inv1 = 1.f / (reds[m0w + gid + 8] + reds[64 + m0w + gid + 8]);
    bool ok0 = (q0 + m0w + gid)     < T_SEQ;
    bool ok1 = (q0 + m0w + gid + 8) < T_SEQ;
    int gr0 = b * T_SEQ + q0 + m0w + gid;
    int gr1 = gr0 + 8;
    #pragma unroll
    for (int ni = 0; ni < 4; ni++) {
        int col = h * HS + cg * 32 + ni * 8 + tig * 2;
        if (ok0)
            *(half2*)(O + (size_t)gr0 * EMBD + poff(gr0, col)) =
                __floats2half2_rn(oacc[ni][0] * inv0, oacc[ni][1] * inv0);
        if (ok1)
            *(half2*)(O + (size_t)gr1 * EMBD + poff(gr1, col)) =
                __floats2half2_rn(oacc[ni][2] * inv1, oacc[ni][3] * inv1);
    }
}

// ---------------- launch ----------------
extern "C" void kernel_launch(void* const* d_in, const int* in_sizes, int n_in,
                              void* d_out, int out_size)
{
    const float* x     = (const float*)d_in[0];
    const float* Wq    = (const float*)d_in[1];
    const float* Wk    = (const float*)d_in[2];
    const float* Wv    = (const float*)d_in[3];
    const float* Wproj = (const float*)d_in[4];
    const float* bproj = (const float*)d_in[5];
    const float* W1    = (const float*)d_in[6];
    const float* b1    = (const float*)d_in[7];
    const float* W2    = (const float*)d_in[8];
    const float* b2    = (const float*)d_in[9];
    const float* g1    = (const float*)d_in[10];
    const float* be1   = (const float*)d_in[11];
    const float* g2    = (const float*)d_in[12];
    const float* be2   = (const float*)d_in[13];

    __half *H, *A, *F, *Wqkvt, *Wpt, *W1t, *W2t;
    float *QKV, *X1;
    cudaGetSymbolAddress((void**)&H,     g_H);
    cudaGetSymbolAddress((void**)&QKV,   g_QKV);
    cudaGetSymbolAddress((void**)&A,     g_A);
    cudaGetSymbolAddress((void**)&X1,    g_X1);
    cudaGetSymbolAddress((void**)&F,     g_F);
    cudaGetSymbolAddress((void**)&Wqkvt, g_Wqkv);
    cudaGetSymbolAddress((void**)&Wpt,   g_Wp);
    cudaGetSymbolAddress((void**)&W1t,   g_W1t);
    cudaGetSymbolAddress((void**)&W2t,   g_W2t);

    cudaFuncSetAttribute(attn2,
                         cudaFuncAttributeMaxDynamicSharedMemorySize, ATTN2_SMEM);

    dim3 blk(256);
    const int nW = (EMBD * EMBD + 255) / 256;
    const int nF = (EMBD * FFN_D + 255) / 256;

    // 0) weight prep
    prep_w<<<nW, 256>>>(Wq,    Wqkvt,                   EMBD, EMBD);
    prep_w<<<nW, 256>>>(Wk,    Wqkvt + EMBD * EMBD,     EMBD, EMBD);
    prep_w<<<nW, 256>>>(Wv,    Wqkvt + 2 * EMBD * EMBD, EMBD, EMBD);
    prep_w<<<nW, 256>>>(Wproj, Wpt,                     EMBD, EMBD);
    prep_w<<<nF, 256>>>(W1,    W1t,                     EMBD, FFN_D);
    prep_w<<<nF, 256>>>(W2,    W2t,                     FFN_D, EMBD);

    // 1) h = LN(x)  -> fp16 permuted
    ln_kernel<<<M_ROWS, 128>>>(x, g1, be1, H);
    // 2) qkv = h @ [Wq|Wk|Wv]  -> fp32 natural
    gemm_h<0><<<dim3(LDQ / 128, M_ROWS / 128), blk>>>(
        H, Wqkvt, nullptr, nullptr, QKV, M_ROWS, LDQ, EMBD);
    // 3) attention -> fp16 permuted
    attn2<<<dim3(4, BATCH * NH), blk, ATTN2_SMEM>>>(QKV, A);
    // 4) x1 = x + att @ Wproj + bproj  -> fp32 natural
    gemm_h<2><<<dim3(EMBD / 128, M_ROWS / 128), blk>>>(
        A, Wpt, bproj, x, X1, M_ROWS, EMBD, EMBD);
    // 5) h2 = LN(x1) -> fp16 permuted
    ln_kernel<<<M_ROWS, 128>>>(X1, g2, be2, H);
    // 6) f = relu(h2 @ W1 + b1) -> fp16 permuted
    gemm_h<1><<<dim3(FFN_D / 128, M_ROWS / 128), blk>>>(
        H, W1t, b1, nullptr, F, M_ROWS, FFN_D, EMBD);
    // 7) out = x1 + f @ W2 + b2 -> fp32 natural
    gemm_h<2><<<dim3(EMBD / 128, M_ROWS / 128), blk>>>(
        F, W2t, b2, X1, (float*)d_out, M_ROWS, EMBD, FFN_D);
}

// round 11
// speedup vs baseline: 4.3833x; 1.1351x over previous
#include <cuda_runtime.h>
#include <cuda_fp16.h>
#include <cstdint>

#define EMBD   384
#define FFN_D  1536
#define T_SEQ  200
#define NH     6
#define HS     64
#define BATCH  256
#define M_ROWS (BATCH * T_SEQ)   // 51200
#define LDQ    1152              // fused QKV row stride

// ---------------- scratch (no allocations allowed) ----------------
__device__ __half g_H [M_ROWS * EMBD];     // LN out, fp16 permuted
__device__ __half g_QKV[M_ROWS * LDQ];     // fp16 natural
__device__ __half g_A [M_ROWS * EMBD];     // attn out, fp16 permuted
__device__ float  g_X1[M_ROWS * EMBD];     // fp32 natural
__device__ __half g_F [M_ROWS * FFN_D];    // relu out, fp16 permuted
// fp16 weights: Wt[N][K], k pair-permuted + chunk-swizzled
__device__ __half g_Wqkv[LDQ * EMBD];
__device__ __half g_Wp  [EMBD * EMBD];
__device__ __half g_W1t [FFN_D * EMBD];
__device__ __half g_W2t [EMBD * FFN_D];

// ---------------- permuted fp16 layout ----------------
// Within each 16-feature block of row m:
//   pair p = (k&15)>>1 -> pp = (p&3)*2 + (p>>2); half h = pp*2 + (k&1);
//   8-byte chunk c = (h>>2) ^ (m&3)  (bank swizzle)
__device__ __forceinline__ int poff(int m, int k) {
    int b = k & 15;
    int p = b >> 1, o = b & 1;
    int pp = ((p & 3) << 1) | (p >> 2);
    int h = (pp << 1) | o;
    int c = (h >> 2) ^ (m & 3);
    return (k & ~15) | (c << 2) | (h & 3);
}

// ---------------- helpers ----------------
__device__ __forceinline__ uint32_t smem_u32(const void* p) {
    uint32_t a;
    asm("{ .reg .u64 t; cvta.to.shared.u64 t, %1; cvt.u32.u64 %0, t; }"
        : "=r"(a) : "l"(p));
    return a;
}
__device__ __forceinline__ void cp16(uint32_t dst, const void* src) {
    asm volatile("cp.async.cg.shared.global [%0], [%1], 16;" :: "r"(dst), "l"(src));
}
#define CP_COMMIT()  asm volatile("cp.async.commit_group;")
#define CP_WAIT(n)   asm volatile("cp.async.wait_group %0;" :: "n"(n))

#define MMA16816(acc, a0, a1, a2, a3, b0, b1)                          \
    asm volatile(                                                      \
        "mma.sync.aligned.m16n8k16.row.col.f32.f16.f16.f32 "           \
        "{%0,%1,%2,%3}, {%4,%5,%6,%7}, {%8,%9}, {%0,%1,%2,%3};"        \
        : "+f"((acc)[0]), "+f"((acc)[1]), "+f"((acc)[2]), "+f"((acc)[3]) \
        : "r"(a0), "r"(a1), "r"(a2), "r"(a3), "r"(b0), "r"(b1))

// ---------------- weight prep ----------------
__global__ void prep_w(const float* __restrict__ src, __half* __restrict__ dst,
                       int K, int N)
{
    int idx = blockIdx.x * 256 + threadIdx.x;
    if (idx >= K * N) return;
    int k = idx / N, n = idx - k * N;
    dst[(size_t)n * K + poff(n, k)] = __float2half(src[idx]);
}

// ---------------- LayerNorm -> fp16 permuted ----------------
__global__ void ln_kernel(const float* __restrict__ x,
                          const float* __restrict__ g,
                          const float* __restrict__ be,
                          __half* __restrict__ out)
{
    __shared__ float red[4];
    int row = blockIdx.x;
    int t = threadIdx.x;
    const float* xr = x + (size_t)row * EMBD;

    float v0 = xr[t], v1 = xr[t + 128], v2 = xr[t + 256];
    float s = v0 + v1 + v2;
    #pragma unroll
    for (int o = 16; o; o >>= 1) s += __shfl_xor_sync(0xffffffffu, s, o);
    if ((t & 31) == 0) red[t >> 5] = s;
    __syncthreads();
    float mean = (red[0] + red[1] + red[2] + red[3]) * (1.0f / EMBD);
    __syncthreads();

    float d0 = v0 - mean, d1 = v1 - mean, d2 = v2 - mean;
    float sq = d0 * d0 + d1 * d1 + d2 * d2;
    #pragma unroll
    for (int o = 16; o; o >>= 1) sq += __shfl_xor_sync(0xffffffffu, sq, o);
    if ((t & 31) == 0) red[t >> 5] = sq;
    __syncthreads();
    float var = (red[0] + red[1] + red[2] + red[3]) * (1.0f / EMBD);
    float inv = rsqrtf(var + 1e-5f);

    __half* orow = out + (size_t)row * EMBD;
    orow[poff(row, t)]       = __float2half(d0 * inv * g[t]       + be[t]);
    orow[poff(row, t + 128)] = __float2half(d1 * inv * g[t + 128] + be[t + 128]);
    orow[poff(row, t + 256)] = __float2half(d2 * inv * g[t + 256] + be[t + 256]);
}

// ---------------- fp16 tensor-core GEMM ----------------
// EPI: 0 = fp16 natural out, 1 = bias+relu (fp16 permuted out),
//      2 = bias+residual (fp32 natural out).
// Single-sync CUTLASS-style 3-stage pipeline.
template <int EPI>
__global__ void __launch_bounds__(256)
gemm_h(const __half* __restrict__ A,
       const __half* __restrict__ Bt,
       const float* __restrict__ bias,
       const float* __restrict__ add,
       void* __restrict__ Cv,
       int M, int N, int K)
{
    __shared__ __half As[3][128 * 32];
    __shared__ __half Bs[3][128 * 32];

    const int tid  = threadIdx.x;
    const int warp = tid >> 5, lane = tid & 31;
    const int wm   = warp >> 1, wn = warp & 1;
    const int gid  = lane >> 2, tig = lane & 3;
    const int m0   = blockIdx.y * 128, n0 = blockIdx.x * 128;

    const int lr = tid >> 1;
    const int lc = (tid & 1) * 32;

    const char* Ag = (const char*)(A + (size_t)(m0 + lr) * K) + lc;
    const char* Bg = (const char*)(Bt + (size_t)(n0 + lr) * K) + lc;
    const uint32_t asm0 = smem_u32(&As[0][0]) + lr * 64 + lc;
    const uint32_t bsm0 = smem_u32(&Bs[0][0]) + lr * 64 + lc;

    float acc[2][8][4];
    #pragma unroll
    for (int i = 0; i < 2; i++)
        #pragma unroll
        for (int j = 0; j < 8; j++)
            #pragma unroll
            for (int l = 0; l < 4; l++) acc[i][j][l] = 0.f;

    const int S = K / 32;

    auto load_stage = [&](int buf, int k0) {
        const char* a = Ag + (size_t)k0 * 2;
        const char* b = Bg + (size_t)k0 * 2;
        uint32_t da = asm0 + buf * 8192, db = bsm0 + buf * 8192;
        cp16(da, a); cp16(da + 16, a + 16);
        cp16(db, b); cp16(db + 16, b + 16);
        CP_COMMIT();
    };

    load_stage(0, 0);
    if (S > 1) load_stage(1, 32); else CP_COMMIT();

    const int cx = ((tig ^ (gid & 3)) << 3);
    const char* asb = (const char*)&As[0][0];
    const char* bsb = (const char*)&Bs[0][0];

    for (int s = 0; s < S; s++) {
        CP_WAIT(1);
        __syncthreads();
        if (s + 2 < S) load_stage((s + 2) % 3, (s + 2) * 32);
        else           CP_COMMIT();

        const char* a_sm = asb + (s % 3) * 8192;
        const char* b_sm = bsb + (s % 3) * 8192;

        #pragma unroll
        for (int blk = 0; blk < 2; blk++) {
            const int bo = blk * 32 + cx;
            uint2 af[2][2];
            #pragma unroll
            for (int mi = 0; mi < 2; mi++) {
                int base = (wm * 32 + mi * 16 + gid) * 64 + bo;
                af[mi][0] = *(const uint2*)(a_sm + base);
                af[mi][1] = *(const uint2*)(a_sm + base + 8 * 64);
            }
            uint2 bf[8];
            #pragma unroll
            for (int ni = 0; ni < 8; ni++)
                bf[ni] = *(const uint2*)(b_sm + (wn * 64 + ni * 8 + gid) * 64 + bo);

            #pragma unroll
            for (int mi = 0; mi < 2; mi++)
                #pragma unroll
                for (int ni = 0; ni < 8; ni++)
                    MMA16816(acc[mi][ni],
                             af[mi][0].x, af[mi][1].x, af[mi][0].y, af[mi][1].y,
                             bf[ni].x, bf[ni].y);
        }
    }

    #pragma unroll
    for (int mi = 0; mi < 2; mi++) {
        int r = m0 + wm * 32 + mi * 16 + gid;
        #pragma unroll
        for (int ni = 0; ni < 8; ni++) {
            int c = n0 + wn * 64 + ni * 8 + tig * 2;
            float v00 = acc[mi][ni][0], v01 = acc[mi][ni][1];
            float v10 = acc[mi][ni][2], v11 = acc[mi][ni][3];
            if (EPI == 0) {
                __half* Ch = (__half*)Cv;
                *(half2*)(Ch + (size_t)r * N + c)       = __floats2half2_rn(v00, v01);
                *(half2*)(Ch + (size_t)(r + 8) * N + c) = __floats2half2_rn(v10, v11);
            } else if (EPI == 1) {
                float bx0 = bias[c], bx1 = bias[c + 1];
                v00 = fmaxf(v00 + bx0, 0.f); v01 = fmaxf(v01 + bx1, 0.f);
                v10 = fmaxf(v10 + bx0, 0.f); v11 = fmaxf(v11 + bx1, 0.f);
                __half* Ch = (__half*)Cv;
                int off = poff(r, c);   // (r+8)&3 == r&3
                *(half2*)(Ch + (size_t)r * N + off)       = __floats2half2_rn(v00, v01);
                *(half2*)(Ch + (size_t)(r + 8) * N + off) = __floats2half2_rn(v10, v11);
            } else {
                float* Cf = (float*)Cv;
                float bx0 = bias[c], bx1 = bias[c + 1];
                float2 r0v = *(const float2*)(add + (size_t)r * N + c);
                float2 r1v = *(const float2*)(add + (size_t)(r + 8) * N + c);
                v00 += bx0 + r0v.x; v01 += bx1 + r0v.y;
                v10 += bx0 + r1v.x; v11 += bx1 + r1v.y;
                *(float2*)(Cf + (size_t)r * N + c)       = make_float2(v00, v01);
                *(float2*)(Cf + (size_t)(r + 8) * N + c) = make_float2(v10, v11);
            }
        }
    }
}

// ---------------- tensor-core attention, one block per (b,h) ----------------
// K/V loaded once; loop over 4 q-tiles with causal tile skipping.
#define KPAD 208
#define AT_K 4096
#define AT_V 16896
#define AT_P 30208
#define AT_RED 43520
#define ATTN3_SMEM (43520 * 2 + 1024)

__global__ void __launch_bounds__(256)
attn3(const __half* __restrict__ QKV, __half* __restrict__ O)
{
    extern __shared__ __half sm2[];
    __half* Qs = sm2;                  // [64][64]
    __half* Ks = sm2 + AT_K;           // [200][64]
    __half* Vt = sm2 + AT_V;           // [64][208]
    __half* Ps = sm2 + AT_P;           // [64][208]
    float* redm = (float*)(sm2 + AT_RED);   // [2][64]
    float* reds = redm + 128;               // [2][64]

    const int bh = blockIdx.x;
    const int b = bh / NH, h = bh % NH;
    const __half* base = QKV + (size_t)b * T_SEQ * LDQ + h * HS;

    const int tid = threadIdx.x, warp = tid >> 5, lane = tid & 31;
    const int gid = lane >> 2, tig = lane & 3;
    const int rg = warp >> 1, cg = warp & 1;
    const int sw = ((tig ^ (gid & 3)) << 3);
    const half2 zz = __floats2half2_rn(0.f, 0.f);

    // ---- K, V(transposed) once per block ----
    for (int i = tid; i < T_SEQ * 32; i += 256) {
        int j = i >> 5, dp = (i & 31) * 2;
        half2 v = *(const half2*)(base + (size_t)j * LDQ + EMBD + dp);
        *(half2*)(Ks + j * 64 + poff(j, dp)) = v;
    }
    for (int i = tid; i < (T_SEQ / 2) * HS; i += 256) {
        int jp = (i >> 6) * 2, d = i & 63;
        __half v0 = base[(size_t)jp * LDQ + 2 * EMBD + d];
        __half v1 = base[(size_t)(jp + 1) * LDQ + 2 * EMBD + d];
        *(half2*)(Vt + d * KPAD + poff(d, jp)) = __halves2half2(v0, v1);
    }
    for (int i = tid; i < HS * 4; i += 256) {
        int d = i >> 2, j = T_SEQ + (i & 3) * 2;
        *(half2*)(Vt + d * KPAD + poff(d, j)) = zz;
    }
    __syncthreads();

    const float scale = 0.05103103630798288f;   // 384^-0.5
    const int m0w = rg * 16;
    const char* qb = (const char*)Qs;
    const char* kbp = (const char*)Ks;
    char* pb = (char*)Ps;
    const char* vb = (const char*)Vt;

    for (int qt = 0; qt < 4; qt++) {
        const int q0 = qt * 64;
        const int jmax = (qt < 3) ? (q0 + 64) : T_SEQ;   // 64,128,192,200
        const int NT = (jmax + 7) >> 3;                   // 8,16,24,25
        const int KB = (jmax + 15) >> 4;                  // 4,8,12,13

        for (int i = tid; i < 64 * 32; i += 256) {
            int r = i >> 5, dp = (i & 31) * 2;
            int gq = q0 + r;
            half2 v = (gq < T_SEQ) ? *(const half2*)(base + (size_t)gq * LDQ + dp) : zz;
            *(half2*)(Qs + r * 64 + poff(r, dp)) = v;
        }
        __syncthreads();

        // ---- S = Q K^T, tiles jt = cg, cg+2, ... < NT ----
        float acc[13][4];
        #pragma unroll
        for (int ii = 0; ii < 13; ii++)
            #pragma unroll
            for (int l = 0; l < 4; l++) acc[ii][l] = 0.f;

        #pragma unroll
        for (int kb = 0; kb < 4; kb++) {
            uint2 a0 = *(const uint2*)(qb + (m0w + gid) * 128 + kb * 32 + sw);
            uint2 a1 = *(const uint2*)(qb + (m0w + gid + 8) * 128 + kb * 32 + sw);
            #pragma unroll
            for (int ii = 0; ii < 13; ii++) {
                int jt = cg + ii * 2;
                if (jt < NT) {
                    uint2 bf = *(const uint2*)(kbp + (jt * 8 + gid) * 128 + kb * 32 + sw);
                    MMA16816(acc[ii], a0.x, a1.x, a0.y, a1.y, bf.x, bf.y);
                }
            }
        }

        // ---- mask + scale + row max ----
        const int r0 = q0 + m0w + gid, r1 = r0 + 8;
        float mx0 = -1e30f, mx1 = -1e30f;
        #pragma unroll
        for (int ii = 0; ii < 13; ii++) {
            int jt = cg + ii * 2;
            if (jt < NT) {
                int j0 = jt * 8 + tig * 2;
                acc[ii][0] = (j0     <= r0) ? acc[ii][0] * scale : -1e30f;
                acc[ii][1] = (j0 + 1 <= r0) ? acc[ii][1] * scale : -1e30f;
                acc[ii][2] = (j0     <= r1) ? acc[ii][2] * scale : -1e30f;
                acc[ii][3] = (j0 + 1 <= r1) ? acc[ii][3] * scale : -1e30f;
                mx0 = fmaxf(mx0, fmaxf(acc[ii][0], acc[ii][1]));
                mx1 = fmaxf(mx1, fmaxf(acc[ii][2], acc[ii][3]));
            }
        }
        mx0 = fmaxf(mx0, __shfl_xor_sync(0xffffffffu, mx0, 1));
        mx0 = fmaxf(mx0, __shfl_xor_sync(0xffffffffu, mx0, 2));
        mx1 = fmaxf(mx1, __shfl_xor_sync(0xffffffffu, mx1, 1));
        mx1 = fmaxf(mx1, __shfl_xor_sync(0xffffffffu, mx1, 2));
        if (tig == 0) {
            redm[cg * 64 + m0w + gid]     = mx0;
            redm[cg * 64 + m0w + gid + 8] = mx1;
        }
        __syncthreads();
        mx0 = fmaxf(redm[m0w + gid],     redm[64 + m0w + gid]);
        mx1 = fmaxf(redm[m0w + gid + 8], redm[64 + m0w + gid + 8]);

        // ---- exp + partial sums + write P ----
        float s0 = 0.f, s1 = 0.f;
        #pragma unroll
        for (int ii = 0; ii < 13; ii++) {
            int jt = cg + ii * 2;
            if (jt < NT) {
                int j0 = jt * 8 + tig * 2;
                float e00 = __expf(acc[ii][0] - mx0), e01 = __expf(acc[ii][1] - mx0);
                float e10 = __expf(acc[ii][2] - mx1), e11 = __expf(acc[ii][3] - mx1);
                s0 += e00 + e01; s1 += e10 + e11;
                int m_ = m0w + gid;
                *(half2*)(pb + m_ * 416 + poff(m_, j0) * 2) = __floats2half2_rn(e00, e01);
                m_ += 8;
                *(half2*)(pb + m_ * 416 + poff(m_, j0) * 2) = __floats2half2_rn(e10, e11);
            }
        }
        if (qt == 3 && cg) {   // zero P tail cols [200,208)
            int j0 = T_SEQ + tig * 2;
            int m_ = m0w + gid;
            *(half2*)(pb + m_ * 416 + poff(m_, j0) * 2) = zz;
            m_ += 8;
            *(half2*)(pb + m_ * 416 + poff(m_, j0) * 2) = zz;
        }
        s0 += __shfl_xor_sync(0xffffffffu, s0, 1);
        s0 += __shfl_xor_sync(0xffffffffu, s0, 2);
        s1 += __shfl_xor_sync(0xffffffffu, s1, 1);
        s1 += __shfl_xor_sync(0xffffffffu, s1, 2);
        if (tig == 0) {
            reds[cg * 64 + m0w + gid]     = s0;
            reds[cg * 64 + m0w + gid + 8] = s1;
        }
        __syncthreads();

        // ---- O = P V, kb < KB ----
        float oacc[4][4];
        #pragma unroll
        for (int ni = 0; ni < 4; ni++)
            #pragma unroll
            for (int l = 0; l < 4; l++) oacc[ni][l] = 0.f;

        #pragma unroll
        for (int kb = 0; kb < 13; kb++) {
            if (kb < KB) {
                uint2 a0 = *(const uint2*)(pb + (m0w + gid) * 416 + kb * 32 + sw);
                uint2 a1 = *(const uint2*)(pb + (m0w + gid + 8) * 416 + kb * 32 + sw);
                #pragma unroll
                for (int ni = 0; ni < 4; ni++) {
                    int d = cg * 32 + ni * 8 + gid;
                    uint2 bf = *(const uint2*)(vb + d * 416 + kb * 32 + sw);
                    MMA16816(oacc[ni], a0.x, a1.x, a0.y, a1.y, bf.x, bf.y);
                }
            }
        }

        float inv0 = 1.f / (reds[m0w + gid]     + reds[64 + m0w + gid]);
        float inv1 = 1.f / (reds[m0w + gid + 8] + reds[64 + m0w + gid + 8]);
        bool ok0 = (q0 + m0w + gid)     < T_SEQ;
        bool ok1 = (q0 + m0w + gid + 8) < T_SEQ;
        int gr0 = b * T_SEQ + q0 + m0w + gid;
        int gr1 = gr0 + 8;
        #pragma unroll
        for (int ni = 0; ni < 4; ni++) {
            int col = h * HS + cg * 32 + ni * 8 + tig * 2;
            if (ok0)
                *(half2*)(O + (size_t)gr0 * EMBD + poff(gr0, col)) =
                    __floats2half2_rn(oacc[ni][0] * inv0, oacc[ni][1] * inv0);
            if (ok1)
                *(half2*)(O + (size_t)gr1 * EMBD + poff(gr1, col)) =
                    __floats2half2_rn(oacc[ni][2] * inv1, oacc[ni][3] * inv1);
        }
    }
}

// ---------------- launch ----------------
extern "C" void kernel_launch(void* const* d_in, const int* in_sizes, int n_in,
                              void* d_out, int out_size)
{
    const float* x     = (const float*)d_in[0];
    const float* Wq    = (const float*)d_in[1];
    const float* Wk    = (const float*)d_in[2];
    const float* Wv    = (const float*)d_in[3];
    const float* Wproj = (const float*)d_in[4];
    const float* bproj = (const float*)d_in[5];
    const float* W1    = (const float*)d_in[6];
    const float* b1    = (const float*)d_in[7];
    const float* W2    = (const float*)d_in[8];
    const float* b2    = (const float*)d_in[9];
    const float* g1    = (const float*)d_in[10];
    const float* be1   = (const float*)d_in[11];
    const float* g2    = (const float*)d_in[12];
    const float* be2   = (const float*)d_in[13];

    __half *H, *QKV, *A, *F, *Wqkvt, *Wpt, *W1t, *W2t;
    float *X1;
    cudaGetSymbolAddress((void**)&H,     g_H);
    cudaGetSymbolAddress((void**)&QKV,   g_QKV);
    cudaGetSymbolAddress((void**)&A,     g_A);
    cudaGetSymbolAddress((void**)&X1,    g_X1);
    cudaGetSymbolAddress((void**)&F,     g_F);
    cudaGetSymbolAddress((void**)&Wqkvt, g_Wqkv);
    cudaGetSymbolAddress((void**)&Wpt,   g_Wp);
    cudaGetSymbolAddress((void**)&W1t,   g_W1t);
    cudaGetSymbolAddress((void**)&W2t,   g_W2t);

    cudaFuncSetAttribute(attn3,
                         cudaFuncAttributeMaxDynamicSharedMemorySize, ATTN3_SMEM);

    dim3 blk(256);
    const int nW = (EMBD * EMBD + 255) / 256;
    const int nF = (EMBD * FFN_D + 255) / 256;

    // 0) weight prep
    prep_w<<<nW, 256>>>(Wq,    Wqkvt,                   EMBD, EMBD);
    prep_w<<<nW, 256>>>(Wk,    Wqkvt + EMBD * EMBD,     EMBD, EMBD);
    prep_w<<<nW, 256>>>(Wv,    Wqkvt + 2 * EMBD * EMBD, EMBD, EMBD);
    prep_w<<<nW, 256>>>(Wproj, Wpt,                     EMBD, EMBD);
    prep_w<<<nF, 256>>>(W1,    W1t,                     EMBD, FFN_D);
    prep_w<<<nF, 256>>>(W2,    W2t,                     FFN_D, EMBD);

    // 1) h = LN(x)  -> fp16 permuted
    ln_kernel<<<M_ROWS, 128>>>(x, g1, be1, H);
    // 2) qkv = h @ [Wq|Wk|Wv]  -> fp16 natural
    gemm_h<0><<<dim3(LDQ / 128, M_ROWS / 128), blk>>>(
        H, Wqkvt, nullptr, nullptr, QKV, M_ROWS, LDQ, EMBD);
    // 3) attention -> fp16 permuted
    attn3<<<BATCH * NH, blk, ATTN3_SMEM>>>(QKV, A);
    // 4) x1 = x + att @ Wproj + bproj  -> fp32 natural
    gemm_h<2><<<dim3(EMBD / 128, M_ROWS / 128), blk>>>(
        A, Wpt, bproj, x, X1, M_ROWS, EMBD, EMBD);
    // 5) h2 = LN(x1) -> fp16 permuted
    ln_kernel<<<M_ROWS, 128>>>(X1, g2, be2, H);
    // 6) f = relu(h2 @ W1 + b1) -> fp16 permuted
    gemm_h<1><<<dim3(FFN_D / 128, M_ROWS / 128), blk>>>(
        H, W1t, b1, nullptr, F, M_ROWS, FFN_D, EMBD);
    // 7) out = x1 + f @ W2 + b2 -> fp32 natural
    gemm_h<2><<<dim3(EMBD / 128, M_ROWS / 128), blk>>>(
        F, W2t, b2, X1, (float*)d_out, M_ROWS, EMBD, FFN_D);
}